// round 1
// baseline (speedup 1.0000x reference)
#include <cuda_runtime.h>
#include <math.h>

#define N_NODES   50000
#define N_EDGES   800000
#define IN_DIM    128
#define EDGE_DIM  16
#define HID       128
#define N_LAYERS  3
#define N_GRAPHS  256
#define MIN_DIM   (HID + EDGE_DIM)   // 144
#define BN_EPS    1e-5f

// ---------------- scratch (static __device__, no allocation) ----------------
__device__ float    g_h[N_NODES * HID];
__device__ float    g_agg[N_NODES * HID];
__device__ float    g_wihT[N_LAYERS * HID * 3 * HID];  // [l][k][o]  o in [0,384)
__device__ float    g_whhT[N_LAYERS * HID * 3 * HID];
__device__ float    g_rsum[N_GRAPHS * HID];
__device__ unsigned g_rmax[N_GRAPHS * HID];
__device__ int      g_rcnt[N_GRAPHS];

// order-preserving float<->uint map for atomicMax over floats
__device__ __forceinline__ unsigned fenc(float f) {
    unsigned u = __float_as_uint(f);
    return (u & 0x80000000u) ? ~u : (u | 0x80000000u);
}
__device__ __forceinline__ float fdec(unsigned k) {
    return __uint_as_float((k & 0x80000000u) ? (k & 0x7fffffffu) : ~k);
}

// ---------------- zeroing ----------------
__global__ void zero_agg_kernel() {
    int i = blockIdx.x * blockDim.x + threadIdx.x;
    float4 z = make_float4(0.f, 0.f, 0.f, 0.f);
    if (i < (N_NODES * HID) / 4) ((float4*)g_agg)[i] = z;
}
__global__ void zero_readout_kernel() {
    int i = blockIdx.x * blockDim.x + threadIdx.x;
    if (i < N_GRAPHS * HID) { g_rsum[i] = 0.f; g_rmax[i] = 0u; }
    if (i < N_GRAPHS) g_rcnt[i] = 0;
}

// ---------------- GRU weight transpose: [l][o][k] -> [l][k][o] ----------------
__global__ void transpose_w_kernel(const float* __restrict__ wih,
                                   const float* __restrict__ whh) {
    int idx = blockIdx.x * blockDim.x + threadIdx.x;
    const int per_layer = 3 * HID * HID;  // 384*128
    if (idx >= N_LAYERS * per_layer) return;
    int l = idx / per_layer;
    int r = idx - l * per_layer;
    int o = r / HID;     // 0..383
    int k = r - o * HID; // 0..127
    g_wihT[l * per_layer + k * (3 * HID) + o] = wih[idx];
    g_whhT[l * per_layer + k * (3 * HID) + o] = whh[idx];
}

// ---------------- input projection: h = relu(x @ W + b) ----------------
// block: 128 threads (one per output channel), 32 nodes per block
#define LIN_NPB 32
#define LIN_SMEM ((IN_DIM * HID + LIN_NPB * IN_DIM) * 4)
__global__ void lin_in_kernel(const float* __restrict__ x,
                              const float* __restrict__ W,
                              const float* __restrict__ b) {
    extern __shared__ float sm[];
    float* sW = sm;                  // 128*128
    float* sX = sm + IN_DIM * HID;   // 32*128
    int tid = threadIdx.x;
    for (int i = tid; i < (IN_DIM * HID) / 4; i += blockDim.x)
        ((float4*)sW)[i] = ((const float4*)W)[i];
    int n0 = blockIdx.x * LIN_NPB;
    int nodes = min(LIN_NPB, N_NODES - n0);
    for (int i = tid; i < (nodes * IN_DIM) / 4; i += blockDim.x)
        ((float4*)sX)[i] = ((const float4*)(x + (size_t)n0 * IN_DIM))[i];
    __syncthreads();

    float acc[LIN_NPB];
#pragma unroll
    for (int e = 0; e < LIN_NPB; e++) acc[e] = 0.f;
    for (int k = 0; k < IN_DIM; k++) {
        float w = sW[k * HID + tid];
#pragma unroll
        for (int e = 0; e < LIN_NPB; e++) acc[e] += w * sX[e * IN_DIM + k];
    }
    float bb = b[tid];
    for (int e = 0; e < nodes; e++)
        g_h[(size_t)(n0 + e) * HID + tid] = fmaxf(acc[e] + bb, 0.f);
}

// ---------------- edge MLP + scatter-add ----------------
// 256 threads: j = tid&127 (out channel), half = tid>>7 handles 16 of the
// 32 edges per tile. Weights resident in SMEM, reused for all tiles.
#define EPB 32
#define EDGE_SMEM ((MIN_DIM * HID + HID * HID + EPB * MIN_DIM + EPB * HID) * 4)
__global__ void edge_mlp_kernel(const float* __restrict__ eattr,
                                const int* __restrict__ src,
                                const int* __restrict__ dst,
                                const float* __restrict__ W1,
                                const float* __restrict__ b1,
                                const float* __restrict__ W2,
                                const float* __restrict__ b2) {
    extern __shared__ float sm[];
    float* sW1  = sm;                        // 144*128
    float* sW2  = sW1 + MIN_DIM * HID;       // 128*128
    float* sMin = sW2 + HID * HID;           // 32*144
    float* sHid = sMin + EPB * MIN_DIM;      // 32*128
    __shared__ int sSrc[EPB];
    __shared__ int sDst[EPB];

    int tid = threadIdx.x;
    int j = tid & 127, half = tid >> 7;

    for (int i = tid; i < (MIN_DIM * HID) / 4; i += 256)
        ((float4*)sW1)[i] = ((const float4*)W1)[i];
    for (int i = tid; i < (HID * HID) / 4; i += 256)
        ((float4*)sW2)[i] = ((const float4*)W2)[i];
    float bb1 = b1[j], bb2 = b2[j];

    const int ntiles = N_EDGES / EPB;  // 25000, exact
    for (int t = blockIdx.x; t < ntiles; t += gridDim.x) {
        int e0 = t * EPB;
        __syncthreads();  // protect sMin/sHid/sSrc reuse from previous tile
        if (tid < EPB) { sSrc[tid] = src[e0 + tid]; sDst[tid] = dst[e0 + tid]; }
        __syncthreads();
        // stage m_in = [h[src] | edge_attr] for 32 edges
        for (int i = tid; i < EPB * MIN_DIM; i += 256) {
            int e = i / MIN_DIM, k = i - e * MIN_DIM;
            sMin[i] = (k < HID) ? g_h[(size_t)sSrc[e] * HID + k]
                                : eattr[(size_t)(e0 + e) * EDGE_DIM + (k - HID)];
        }
        __syncthreads();

        // stage 1: hidden = relu(m_in @ W1 + b1)
        float acc[16];
#pragma unroll
        for (int e = 0; e < 16; e++) acc[e] = 0.f;
        const float* mb = sMin + half * 16 * MIN_DIM;
        for (int k = 0; k < MIN_DIM; k++) {
            float w = sW1[k * HID + j];
#pragma unroll
            for (int e = 0; e < 16; e++) acc[e] += w * mb[e * MIN_DIM + k];
        }
        float* hb = sHid + half * 16 * HID;
#pragma unroll
        for (int e = 0; e < 16; e++) hb[e * HID + j] = fmaxf(acc[e] + bb1, 0.f);
        __syncthreads();

        // stage 2: m = hidden @ W2 + b2, scatter-add into agg[dst]
#pragma unroll
        for (int e = 0; e < 16; e++) acc[e] = 0.f;
        for (int k = 0; k < HID; k++) {
            float w = sW2[k * HID + j];
#pragma unroll
            for (int e = 0; e < 16; e++) acc[e] += w * hb[e * HID + k];
        }
#pragma unroll
        for (int e = 0; e < 16; e++)
            atomicAdd(&g_agg[(size_t)sDst[half * 16 + e] * HID + j], acc[e] + bb2);
    }
}

// ---------------- GRU + BN + residual ----------------
// 384 threads (one per gate-output o in [0,384)), 16 nodes per block.
#define GRU_NPB 16
#define GRU_SMEM ((GRU_NPB * HID * 2 + GRU_NPB * 3 * HID * 2) * 4)
__global__ void gru_kernel(int l,
                           const float* __restrict__ bih,
                           const float* __restrict__ bhh,
                           const float* __restrict__ gamma,
                           const float* __restrict__ beta,
                           const float* __restrict__ mean,
                           const float* __restrict__ var) {
    extern __shared__ float sm[];
    float* sA  = sm;                   // 16*128
    float* sH  = sA + GRU_NPB * HID;   // 16*128
    float* sGi = sH + GRU_NPB * HID;   // 16*384
    float* sGh = sGi + GRU_NPB * 3 * HID;

    int tid = threadIdx.x;  // 384
    int n0 = blockIdx.x * GRU_NPB;
    const float* wiT = g_wihT + (size_t)l * HID * 3 * HID;
    const float* whT = g_whhT + (size_t)l * HID * 3 * HID;

    for (int i = tid; i < (GRU_NPB * HID) / 4; i += blockDim.x) {
        ((float4*)sA)[i] = ((const float4*)(g_agg + (size_t)n0 * HID))[i];
        ((float4*)sH)[i] = ((const float4*)(g_h + (size_t)n0 * HID))[i];
    }
    __syncthreads();

    float ai[GRU_NPB], ah[GRU_NPB];
#pragma unroll
    for (int e = 0; e < GRU_NPB; e++) { ai[e] = 0.f; ah[e] = 0.f; }
    for (int k = 0; k < HID; k++) {
        float wi = wiT[k * 384 + tid];
        float wh = whT[k * 384 + tid];
#pragma unroll
        for (int e = 0; e < GRU_NPB; e++) {
            ai[e] += wi * sA[e * HID + k];
            ah[e] += wh * sH[e * HID + k];
        }
    }
    float bi = bih[tid], bh = bhh[tid];
#pragma unroll
    for (int e = 0; e < GRU_NPB; e++) {
        sGi[e * 384 + tid] = ai[e] + bi;
        sGh[e * 384 + tid] = ah[e] + bh;
    }
    __syncthreads();

    if (tid < 256) {
        int j = tid & 127, eo = tid >> 7;
        float gm = gamma[j], bt = beta[j], mu = mean[j];
        float inv = rsqrtf(var[j] + BN_EPS);
        for (int e = eo; e < GRU_NPB; e += 2) {
            float ir = sGi[e * 384 + j],       hr = sGh[e * 384 + j];
            float iz = sGi[e * 384 + 128 + j], hz = sGh[e * 384 + 128 + j];
            float in = sGi[e * 384 + 256 + j], hn = sGh[e * 384 + 256 + j];
            float r = 1.f / (1.f + __expf(-(ir + hr)));
            float z = 1.f / (1.f + __expf(-(iz + hz)));
            float nn = tanhf(in + r * hn);
            float hold = sH[e * HID + j];
            float hnew = (1.f - z) * nn + z * hold;
            float bn = (hnew - mu) * inv * gm + bt;
            g_h[(size_t)(n0 + e) * HID + j] = hold + bn;
        }
    }
}

// ---------------- readout accumulation ----------------
__global__ void readout_acc_kernel(const int* __restrict__ batch) {
    int idx = blockIdx.x * blockDim.x + threadIdx.x;
    if (idx >= N_NODES * HID) return;
    int n = idx >> 7, j = idx & 127;
    int b = batch[n];
    float v = g_h[idx];
    atomicAdd(&g_rsum[b * HID + j], v);
    atomicMax(&g_rmax[b * HID + j], fenc(v));
    if (j == 0) atomicAdd(&g_rcnt[b], 1);
}

// ---------------- readout final: relu([mean|max] @ ro_w + ro_b) ----------------
__global__ void readout_final_kernel(const float* __restrict__ roW,
                                     const float* __restrict__ roB,
                                     float* __restrict__ out) {
    __shared__ float s[2 * HID];
    int g = blockIdx.x, j = threadIdx.x;
    int cnt = g_rcnt[g];
    float mv = g_rsum[g * HID + j] / fmaxf((float)cnt, 1.f);
    float xv = (cnt > 0) ? fdec(g_rmax[g * HID + j]) : 0.f;
    s[j] = mv;
    s[HID + j] = xv;
    __syncthreads();
    float acc = roB[j];
    for (int k = 0; k < 2 * HID; k++) acc += s[k] * roW[k * HID + j];
    out[g * HID + j] = fmaxf(acc, 0.f);
}

// ---------------- launch ----------------
extern "C" void kernel_launch(void* const* d_in, const int* in_sizes, int n_in,
                              void* d_out, int out_size) {
    // n_graphs may appear as a tiny scalar input at index 4
    int base = (in_sizes[4] <= 2) ? 5 : 4;
    const float* x     = (const float*)d_in[0];
    const int*   eidx  = (const int*)d_in[1];
    const float* eattr = (const float*)d_in[2];
    const int*   batch = (const int*)d_in[3];
    const float* linW  = (const float*)d_in[base + 0];
    const float* linB  = (const float*)d_in[base + 1];
    const float* w1    = (const float*)d_in[base + 2];
    const float* b1    = (const float*)d_in[base + 3];
    const float* w2    = (const float*)d_in[base + 4];
    const float* b2    = (const float*)d_in[base + 5];
    const float* bng   = (const float*)d_in[base + 6];
    const float* bnb   = (const float*)d_in[base + 7];
    const float* bnm   = (const float*)d_in[base + 8];
    const float* bnv   = (const float*)d_in[base + 9];
    const float* wih   = (const float*)d_in[base + 10];
    const float* whh   = (const float*)d_in[base + 11];
    const float* bih   = (const float*)d_in[base + 12];
    const float* bhh   = (const float*)d_in[base + 13];
    const float* roW   = (const float*)d_in[base + 14];
    const float* roB   = (const float*)d_in[base + 15];
    float* out = (float*)d_out;

    cudaFuncSetAttribute(lin_in_kernel,   cudaFuncAttributeMaxDynamicSharedMemorySize, LIN_SMEM);
    cudaFuncSetAttribute(edge_mlp_kernel, cudaFuncAttributeMaxDynamicSharedMemorySize, EDGE_SMEM);
    cudaFuncSetAttribute(gru_kernel,      cudaFuncAttributeMaxDynamicSharedMemorySize, GRU_SMEM);

    lin_in_kernel<<<(N_NODES + LIN_NPB - 1) / LIN_NPB, 128, LIN_SMEM>>>(x, linW, linB);
    transpose_w_kernel<<<(N_LAYERS * 3 * HID * HID + 255) / 256, 256>>>(wih, whh);

    for (int l = 0; l < N_LAYERS; l++) {
        zero_agg_kernel<<<(N_NODES * HID / 4 + 255) / 256, 256>>>();
        edge_mlp_kernel<<<148, 256, EDGE_SMEM>>>(
            eattr, eidx, eidx + N_EDGES,
            w1 + (size_t)l * MIN_DIM * HID, b1 + l * HID,
            w2 + (size_t)l * HID * HID,     b2 + l * HID);
        gru_kernel<<<N_NODES / GRU_NPB, 384, GRU_SMEM>>>(
            l, bih + l * 3 * HID, bhh + l * 3 * HID,
            bng + l * HID, bnb + l * HID, bnm + l * HID, bnv + l * HID);
    }

    zero_readout_kernel<<<(N_GRAPHS * HID + 255) / 256, 256>>>();
    readout_acc_kernel<<<(N_NODES * HID + 255) / 256, 256>>>(batch);
    readout_final_kernel<<<N_GRAPHS, HID>>>(roW, roB, out);
}

// round 3
// speedup vs baseline: 1.8078x; 1.8078x over previous
#include <cuda_runtime.h>
#include <math.h>

#define N_NODES   50000
#define N_EDGES   800000
#define IN_DIM    128
#define EDGE_DIM  16
#define HID       128
#define N_LAYERS  3
#define N_GRAPHS  256
#define MIN_DIM   (HID + EDGE_DIM)   // 144
#define BN_EPS    1e-5f

// ---------------- scratch (static __device__, no allocation) ----------------
__device__ float    g_h[N_NODES * HID];
__device__ float    g_agg[N_NODES * HID];
__device__ float    g_wihT[N_LAYERS * HID * 3 * HID];  // [l][k][o]
__device__ float    g_whhT[N_LAYERS * HID * 3 * HID];
__device__ float    g_rsum[N_GRAPHS * HID];
__device__ unsigned g_rmax[N_GRAPHS * HID];
__device__ int      g_rcnt[N_GRAPHS];

// order-preserving float<->uint map for atomicMax over floats
__device__ __forceinline__ unsigned fenc(float f) {
    unsigned u = __float_as_uint(f);
    return (u & 0x80000000u) ? ~u : (u | 0x80000000u);
}
__device__ __forceinline__ float fdec(unsigned k) {
    return __uint_as_float((k & 0x80000000u) ? (k & 0x7fffffffu) : ~k);
}

__device__ __forceinline__ unsigned f2tf(float f) {
    unsigned u;
    asm("cvt.rna.tf32.f32 %0, %1;" : "=r"(u) : "f"(f));
    return u;
}

__device__ __forceinline__ void mma_tf32(float* c, const unsigned* a,
                                         unsigned b0, unsigned b1) {
    asm volatile(
        "mma.sync.aligned.m16n8k8.row.col.f32.tf32.tf32.f32 "
        "{%0,%1,%2,%3}, {%4,%5,%6,%7}, {%8,%9}, {%0,%1,%2,%3};"
        : "+f"(c[0]), "+f"(c[1]), "+f"(c[2]), "+f"(c[3])
        : "r"(a[0]), "r"(a[1]), "r"(a[2]), "r"(a[3]), "r"(b0), "r"(b1));
}

// ---------------- zeroing ----------------
__global__ void zero_agg_kernel() {
    int i = blockIdx.x * blockDim.x + threadIdx.x;
    float4 z = make_float4(0.f, 0.f, 0.f, 0.f);
    if (i < (N_NODES * HID) / 4) ((float4*)g_agg)[i] = z;
}
__global__ void zero_readout_kernel() {
    int i = blockIdx.x * blockDim.x + threadIdx.x;
    if (i < N_GRAPHS * HID) { g_rsum[i] = 0.f; g_rmax[i] = 0u; }
    if (i < N_GRAPHS) g_rcnt[i] = 0;
}

// ---------------- GRU weight transpose: [l][o][k] -> [l][k][o] ----------------
__global__ void transpose_w_kernel(const float* __restrict__ wih,
                                   const float* __restrict__ whh) {
    int idx = blockIdx.x * blockDim.x + threadIdx.x;
    const int per_layer = 3 * HID * HID;
    if (idx >= N_LAYERS * per_layer) return;
    int l = idx / per_layer;
    int r = idx - l * per_layer;
    int o = r / HID;
    int k = r - o * HID;
    g_wihT[l * per_layer + k * (3 * HID) + o] = wih[idx];
    g_whhT[l * per_layer + k * (3 * HID) + o] = whh[idx];
}

// ---------------- input projection: h = relu(x @ W + b) ----------------
#define LIN_NPB 32
#define LIN_SMEM ((IN_DIM * HID + LIN_NPB * IN_DIM) * 4)
__global__ void lin_in_kernel(const float* __restrict__ x,
                              const float* __restrict__ W,
                              const float* __restrict__ b) {
    extern __shared__ float sm[];
    float* sW = sm;
    float* sX = sm + IN_DIM * HID;
    int tid = threadIdx.x;
    for (int i = tid; i < (IN_DIM * HID) / 4; i += blockDim.x)
        ((float4*)sW)[i] = ((const float4*)W)[i];
    int n0 = blockIdx.x * LIN_NPB;
    int nodes = min(LIN_NPB, N_NODES - n0);
    for (int i = tid; i < (nodes * IN_DIM) / 4; i += blockDim.x)
        ((float4*)sX)[i] = ((const float4*)(x + (size_t)n0 * IN_DIM))[i];
    __syncthreads();

    float acc[LIN_NPB];
#pragma unroll
    for (int e = 0; e < LIN_NPB; e++) acc[e] = 0.f;
    for (int k = 0; k < IN_DIM; k++) {
        float w = sW[k * HID + tid];
#pragma unroll
        for (int e = 0; e < LIN_NPB; e++) acc[e] += w * sX[e * IN_DIM + k];
    }
    float bb = b[tid];
    for (int e = 0; e < nodes; e++)
        g_h[(size_t)(n0 + e) * HID + tid] = fmaxf(acc[e] + bb, 0.f);
}

// ---------------- edge MLP on tensor cores (tf32 mma.sync) ----------------
// BM=128 edges, BN=128. 8 warps (4M x 2N). Weights persist in SMEM (tf32).
// SMEM: sW1[144x132] | sW2[128x132] | sA[128x148] (overlaid by sHid[128x132])
#define LDA1 148
#define LDA2 132
#define LDW  132
#define EDGE_TF_SMEM ((144 * LDW + 128 * LDW + 128 * LDA1) * 4)

__global__ void __launch_bounds__(256, 1)
edge_mma_kernel(const float* __restrict__ eattr,
                const int* __restrict__ src,
                const int* __restrict__ dst,
                const float* __restrict__ W1,
                const float* __restrict__ b1,
                const float* __restrict__ W2,
                const float* __restrict__ b2) {
    extern __shared__ unsigned smu[];
    unsigned* sW1 = smu;                 // 144 x 132
    unsigned* sW2 = sW1 + 144 * LDW;     // 128 x 132
    unsigned* sA  = sW2 + 128 * LDW;     // 128 x 148 (tf32 bits)
    unsigned* sHid = sA;                 // overlay: 128 x 132
    __shared__ float sB1[128], sB2[128];

    int tid  = threadIdx.x;
    int lane = tid & 31;
    int wid  = tid >> 5;
    int wm   = wid & 3;   // warp M index (rows wm*32 .. +32)
    int wn   = wid >> 2;  // warp N index (cols wn*64 .. +64)
    int gid  = lane >> 2; // group id 0..7
    int tg   = lane & 3;  // thread in group 0..3

    // stage weights into SMEM (tf32 converted)
    for (int i = tid; i < MIN_DIM * HID; i += 256) {
        int r = i >> 7, c = i & 127;
        sW1[r * LDW + c] = f2tf(W1[i]);
    }
    for (int i = tid; i < HID * HID; i += 256) {
        int r = i >> 7, c = i & 127;
        sW2[r * LDW + c] = f2tf(W2[i]);
    }
    if (tid < 128) { sB1[tid] = b1[tid]; sB2[tid] = b2[tid]; }

    const int ntiles = N_EDGES / 128;  // 6250
    for (int t = blockIdx.x; t < ntiles; t += gridDim.x) {
        int e0 = t * 128;
        __syncthreads();  // previous tile's stage2 reads of sHid are done

        // gather m_in = [h[src] | edge_attr] (tf32) : warp w loads rows w, w+8, ...
        for (int r = wid; r < 128; r += 8) {
            int s = src[e0 + r];
            const float* hrow = g_h + (size_t)s * HID;
            for (int c = lane; c < HID; c += 32)
                sA[r * LDA1 + c] = f2tf(hrow[c]);
            if (lane < EDGE_DIM)
                sA[r * LDA1 + HID + lane] =
                    f2tf(eattr[(size_t)(e0 + r) * EDGE_DIM + lane]);
        }
        __syncthreads();

        // ---- stage 1: hidden = relu(m_in @ W1 + b1), K=144 ----
        float acc[2][8][4];
#pragma unroll
        for (int mt = 0; mt < 2; mt++)
#pragma unroll
            for (int nt = 0; nt < 8; nt++)
#pragma unroll
                for (int i = 0; i < 4; i++) acc[mt][nt][i] = 0.f;

        for (int ks = 0; ks < 18; ks++) {
            unsigned a[2][4];
#pragma unroll
            for (int mt = 0; mt < 2; mt++) {
                int R = wm * 32 + mt * 16 + gid;
                int col = ks * 8 + tg;
                a[mt][0] = sA[R * LDA1 + col];
                a[mt][1] = sA[(R + 8) * LDA1 + col];
                a[mt][2] = sA[R * LDA1 + col + 4];
                a[mt][3] = sA[(R + 8) * LDA1 + col + 4];
            }
#pragma unroll
            for (int nt = 0; nt < 8; nt++) {
                int C = wn * 64 + nt * 8 + gid;
                unsigned b0 = sW1[(ks * 8 + tg) * LDW + C];
                unsigned b1r = sW1[(ks * 8 + tg + 4) * LDW + C];
                mma_tf32(acc[0][nt], a[0], b0, b1r);
                mma_tf32(acc[1][nt], a[1], b0, b1r);
            }
        }
        __syncthreads();  // all warps done reading sA

        // bias + relu + tf32, store into sHid (overlays sA)
#pragma unroll
        for (int mt = 0; mt < 2; mt++)
#pragma unroll
            for (int nt = 0; nt < 8; nt++)
#pragma unroll
                for (int i = 0; i < 4; i++) {
                    int row = wm * 32 + mt * 16 + gid + ((i >> 1) << 3);
                    int col = wn * 64 + nt * 8 + 2 * tg + (i & 1);
                    float v = fmaxf(acc[mt][nt][i] + sB1[col], 0.f);
                    sHid[row * LDA2 + col] = f2tf(v);
                }
        __syncthreads();

        // ---- stage 2: m = hidden @ W2 + b2, K=128 ----
#pragma unroll
        for (int mt = 0; mt < 2; mt++)
#pragma unroll
            for (int nt = 0; nt < 8; nt++)
#pragma unroll
                for (int i = 0; i < 4; i++) acc[mt][nt][i] = 0.f;

        for (int ks = 0; ks < 16; ks++) {
            unsigned a[2][4];
#pragma unroll
            for (int mt = 0; mt < 2; mt++) {
                int R = wm * 32 + mt * 16 + gid;
                int col = ks * 8 + tg;
                a[mt][0] = sHid[R * LDA2 + col];
                a[mt][1] = sHid[(R + 8) * LDA2 + col];
                a[mt][2] = sHid[R * LDA2 + col + 4];
                a[mt][3] = sHid[(R + 8) * LDA2 + col + 4];
            }
#pragma unroll
            for (int nt = 0; nt < 8; nt++) {
                int C = wn * 64 + nt * 8 + gid;
                unsigned b0 = sW2[(ks * 8 + tg) * LDW + C];
                unsigned b1r = sW2[(ks * 8 + tg + 4) * LDW + C];
                mma_tf32(acc[0][nt], a[0], b0, b1r);
                mma_tf32(acc[1][nt], a[1], b0, b1r);
            }
        }

        // epilogue: scatter-add into g_agg[dst]
        int drow[4];
#pragma unroll
        for (int mt = 0; mt < 2; mt++) {
            drow[mt * 2]     = dst[e0 + wm * 32 + mt * 16 + gid];
            drow[mt * 2 + 1] = dst[e0 + wm * 32 + mt * 16 + gid + 8];
        }
#pragma unroll
        for (int mt = 0; mt < 2; mt++)
#pragma unroll
            for (int nt = 0; nt < 8; nt++)
#pragma unroll
                for (int i = 0; i < 4; i++) {
                    int d = drow[mt * 2 + (i >> 1)];
                    int col = wn * 64 + nt * 8 + 2 * tg + (i & 1);
                    atomicAdd(&g_agg[(size_t)d * HID + col],
                              acc[mt][nt][i] + sB2[col]);
                }
    }
}

// ---------------- GRU + BN + residual ----------------
#define GRU_NPB 16
#define GRU_SMEM ((GRU_NPB * HID * 2 + GRU_NPB * 3 * HID * 2) * 4)
__global__ void gru_kernel(int l,
                           const float* __restrict__ bih,
                           const float* __restrict__ bhh,
                           const float* __restrict__ gamma,
                           const float* __restrict__ beta,
                           const float* __restrict__ mean,
                           const float* __restrict__ var) {
    extern __shared__ float sm[];
    float* sA  = sm;
    float* sH  = sA + GRU_NPB * HID;
    float* sGi = sH + GRU_NPB * HID;
    float* sGh = sGi + GRU_NPB * 3 * HID;

    int tid = threadIdx.x;  // 384
    int n0 = blockIdx.x * GRU_NPB;
    const float* wiT = g_wihT + (size_t)l * HID * 3 * HID;
    const float* whT = g_whhT + (size_t)l * HID * 3 * HID;

    for (int i = tid; i < (GRU_NPB * HID) / 4; i += blockDim.x) {
        ((float4*)sA)[i] = ((const float4*)(g_agg + (size_t)n0 * HID))[i];
        ((float4*)sH)[i] = ((const float4*)(g_h + (size_t)n0 * HID))[i];
    }
    __syncthreads();

    float ai[GRU_NPB], ah[GRU_NPB];
#pragma unroll
    for (int e = 0; e < GRU_NPB; e++) { ai[e] = 0.f; ah[e] = 0.f; }
    for (int k = 0; k < HID; k++) {
        float wi = wiT[k * 384 + tid];
        float wh = whT[k * 384 + tid];
#pragma unroll
        for (int e = 0; e < GRU_NPB; e++) {
            ai[e] += wi * sA[e * HID + k];
            ah[e] += wh * sH[e * HID + k];
        }
    }
    float bi = bih[tid], bh = bhh[tid];
#pragma unroll
    for (int e = 0; e < GRU_NPB; e++) {
        sGi[e * 384 + tid] = ai[e] + bi;
        sGh[e * 384 + tid] = ah[e] + bh;
    }
    __syncthreads();

    if (tid < 256) {
        int j = tid & 127, eo = tid >> 7;
        float gm = gamma[j], bt = beta[j], mu = mean[j];
        float inv = rsqrtf(var[j] + BN_EPS);
        for (int e = eo; e < GRU_NPB; e += 2) {
            float ir = sGi[e * 384 + j],       hr = sGh[e * 384 + j];
            float iz = sGi[e * 384 + 128 + j], hz = sGh[e * 384 + 128 + j];
            float in = sGi[e * 384 + 256 + j], hn = sGh[e * 384 + 256 + j];
            float r = 1.f / (1.f + __expf(-(ir + hr)));
            float z = 1.f / (1.f + __expf(-(iz + hz)));
            float nn = tanhf(in + r * hn);
            float hold = sH[e * HID + j];
            float hnew = (1.f - z) * nn + z * hold;
            float bn = (hnew - mu) * inv * gm + bt;
            g_h[(size_t)(n0 + e) * HID + j] = hold + bn;
        }
    }
}

// ---------------- readout accumulation ----------------
__global__ void readout_acc_kernel(const int* __restrict__ batch) {
    int idx = blockIdx.x * blockDim.x + threadIdx.x;
    if (idx >= N_NODES * HID) return;
    int n = idx >> 7, j = idx & 127;
    int b = batch[n];
    float v = g_h[idx];
    atomicAdd(&g_rsum[b * HID + j], v);
    atomicMax(&g_rmax[b * HID + j], fenc(v));
    if (j == 0) atomicAdd(&g_rcnt[b], 1);
}

// ---------------- readout final ----------------
__global__ void readout_final_kernel(const float* __restrict__ roW,
                                     const float* __restrict__ roB,
                                     float* __restrict__ out) {
    __shared__ float s[2 * HID];
    int g = blockIdx.x, j = threadIdx.x;
    int cnt = g_rcnt[g];
    float mv = g_rsum[g * HID + j] / fmaxf((float)cnt, 1.f);
    float xv = (cnt > 0) ? fdec(g_rmax[g * HID + j]) : 0.f;
    s[j] = mv;
    s[HID + j] = xv;
    __syncthreads();
    float acc = roB[j];
    for (int k = 0; k < 2 * HID; k++) acc += s[k] * roW[k * HID + j];
    out[g * HID + j] = fmaxf(acc, 0.f);
}

// ---------------- launch ----------------
extern "C" void kernel_launch(void* const* d_in, const int* in_sizes, int n_in,
                              void* d_out, int out_size) {
    int base = (in_sizes[4] <= 2) ? 5 : 4;
    const float* x     = (const float*)d_in[0];
    const int*   eidx  = (const int*)d_in[1];
    const float* eattr = (const float*)d_in[2];
    const int*   batch = (const int*)d_in[3];
    const float* linW  = (const float*)d_in[base + 0];
    const float* linB  = (const float*)d_in[base + 1];
    const float* w1    = (const float*)d_in[base + 2];
    const float* b1    = (const float*)d_in[base + 3];
    const float* w2    = (const float*)d_in[base + 4];
    const float* b2    = (const float*)d_in[base + 5];
    const float* bng   = (const float*)d_in[base + 6];
    const float* bnb   = (const float*)d_in[base + 7];
    const float* bnm   = (const float*)d_in[base + 8];
    const float* bnv   = (const float*)d_in[base + 9];
    const float* wih   = (const float*)d_in[base + 10];
    const float* whh   = (const float*)d_in[base + 11];
    const float* bih   = (const float*)d_in[base + 12];
    const float* bhh   = (const float*)d_in[base + 13];
    const float* roW   = (const float*)d_in[base + 14];
    const float* roB   = (const float*)d_in[base + 15];
    float* out = (float*)d_out;

    cudaFuncSetAttribute(lin_in_kernel,   cudaFuncAttributeMaxDynamicSharedMemorySize, LIN_SMEM);
    cudaFuncSetAttribute(edge_mma_kernel, cudaFuncAttributeMaxDynamicSharedMemorySize, EDGE_TF_SMEM);
    cudaFuncSetAttribute(gru_kernel,      cudaFuncAttributeMaxDynamicSharedMemorySize, GRU_SMEM);

    lin_in_kernel<<<(N_NODES + LIN_NPB - 1) / LIN_NPB, 128, LIN_SMEM>>>(x, linW, linB);
    transpose_w_kernel<<<(N_LAYERS * 3 * HID * HID + 255) / 256, 256>>>(wih, whh);

    for (int l = 0; l < N_LAYERS; l++) {
        zero_agg_kernel<<<(N_NODES * HID / 4 + 255) / 256, 256>>>();
        edge_mma_kernel<<<148, 256, EDGE_TF_SMEM>>>(
            eattr, eidx, eidx + N_EDGES,
            w1 + (size_t)l * MIN_DIM * HID, b1 + l * HID,
            w2 + (size_t)l * HID * HID,     b2 + l * HID);
        gru_kernel<<<N_NODES / GRU_NPB, 384, GRU_SMEM>>>(
            l, bih + l * 3 * HID, bhh + l * 3 * HID,
            bng + l * HID, bnb + l * HID, bnm + l * HID, bnv + l * HID);
    }

    zero_readout_kernel<<<(N_GRAPHS * HID + 255) / 256, 256>>>();
    readout_acc_kernel<<<(N_NODES * HID + 255) / 256, 256>>>(batch);
    readout_final_kernel<<<N_GRAPHS, HID>>>(roW, roB, out);
}

// round 4
// speedup vs baseline: 5.0434x; 2.7898x over previous
#include <cuda_runtime.h>
#include <math.h>
#include <stdint.h>

#define N_NODES   50000
#define N_EDGES   800000
#define IN_DIM    128
#define EDGE_DIM  16
#define HID       128
#define N_LAYERS  3
#define N_GRAPHS  256
#define BN_EPS    1e-5f

// ---------------- scratch (static __device__, no allocation) ----------------
__device__ float    g_h[N_NODES * HID];
__device__ float    g_agg[N_NODES * HID];
__device__ float    g_p[N_NODES * HID];            // P = h@W1h + b1
__device__ float    g_gi[N_NODES * 3 * HID];
__device__ float    g_gh[N_NODES * 3 * HID];
__device__ float    g_wihT[N_LAYERS * HID * 3 * HID];  // [l][k][o]
__device__ float    g_whhT[N_LAYERS * HID * 3 * HID];
__device__ float    g_rsum[N_GRAPHS * HID];
__device__ unsigned g_rmax[N_GRAPHS * HID];
__device__ int      g_rcnt[N_GRAPHS];

// ---------------- helpers ----------------
__device__ __forceinline__ unsigned fenc(float f) {
    unsigned u = __float_as_uint(f);
    return (u & 0x80000000u) ? ~u : (u | 0x80000000u);
}
__device__ __forceinline__ float fdec(unsigned k) {
    return __uint_as_float((k & 0x80000000u) ? (k & 0x7fffffffu) : ~k);
}
__device__ __forceinline__ unsigned f2tf(float f) {
    unsigned u;
    asm("cvt.rna.tf32.f32 %0, %1;" : "=r"(u) : "f"(f));
    return u;
}
__device__ __forceinline__ void mma_tf32(float* c, const unsigned* a,
                                         unsigned b0, unsigned b1) {
    asm volatile(
        "mma.sync.aligned.m16n8k8.row.col.f32.tf32.tf32.f32 "
        "{%0,%1,%2,%3}, {%4,%5,%6,%7}, {%8,%9}, {%0,%1,%2,%3};"
        : "+f"(c[0]), "+f"(c[1]), "+f"(c[2]), "+f"(c[3])
        : "r"(a[0]), "r"(a[1]), "r"(a[2]), "r"(a[3]), "r"(b0), "r"(b1));
}
__device__ __forceinline__ void cp16(uint32_t s, const void* g) {
    asm volatile("cp.async.cg.shared.global [%0], [%1], 16;" :: "r"(s), "l"(g));
}
__device__ __forceinline__ void red4(float* p, float4 v) {
    asm volatile("red.global.add.v4.f32 [%0], {%1,%2,%3,%4};"
                 :: "l"(p), "f"(v.x), "f"(v.y), "f"(v.z), "f"(v.w) : "memory");
}

// ---------------- zero / setup ----------------
__global__ void zero_agg_kernel() {
    int i = blockIdx.x * blockDim.x + threadIdx.x;
    if (i < (N_NODES * HID) / 4)
        ((float4*)g_agg)[i] = make_float4(0.f, 0.f, 0.f, 0.f);
}
__global__ void zero_readout_kernel() {
    int i = blockIdx.x * blockDim.x + threadIdx.x;
    if (i < N_GRAPHS * HID) { g_rsum[i] = 0.f; g_rmax[i] = 0u; }
    if (i < N_GRAPHS) g_rcnt[i] = 0;
}
__global__ void transpose_w_kernel(const float* __restrict__ wih,
                                   const float* __restrict__ whh) {
    int idx = blockIdx.x * blockDim.x + threadIdx.x;
    const int per_layer = 3 * HID * HID;
    if (idx >= N_LAYERS * per_layer) return;
    int l = idx / per_layer;
    int r = idx - l * per_layer;
    int o = r / HID;
    int k = r - o * HID;
    g_wihT[l * per_layer + k * (3 * HID) + o] = wih[idx];
    g_whhT[l * per_layer + k * (3 * HID) + o] = whh[idx];
}

// ---------------- dense tf32 GEMM: C[M,Ntot] = act(A[M,128] @ B[128,Ntot] + bias)
// BM=64, BN=128, K=128 single slab. 8 warps (4M x 2N). 2 CTAs/SM.
#define DEN_SMEM ((64 * 132 + 128 * 132) * 4)
__global__ void __launch_bounds__(256, 2)
dense_mma(const float* __restrict__ A, const float* __restrict__ B,
          const float* __restrict__ bias, float* __restrict__ C,
          int M, int Ntot, int do_relu) {
    extern __shared__ unsigned dsm[];
    float*    sA = (float*)dsm;        // 64 x 132 (raw fp32 bits as tf32)
    unsigned* sB = dsm + 64 * 132;     // 128 x 132 (tf32)
    int tid = threadIdx.x, lane = tid & 31, wid = tid >> 5;
    int wm = wid & 3, wn = wid >> 2, gid = lane >> 2, tg = lane & 3;
    int m0 = blockIdx.x * 64, n0 = blockIdx.y * 128;

#pragma unroll
    for (int i = 0; i < 8; i++) {
        int idx = tid + i * 256;          // 2048 float4 total
        int r = idx >> 5, c4 = idx & 31;
        int gm = m0 + r; if (gm >= M) gm = M - 1;
        float4 v = __ldg((const float4*)(A + (size_t)gm * 128) + c4);
        *(float4*)(sA + r * 132 + c4 * 4) = v;
    }
    for (int i = tid; i < 128 * 128; i += 256) {
        int k = i >> 7, c = i & 127;
        sB[k * 132 + c] = f2tf(__ldg(B + (size_t)k * Ntot + n0 + c));
    }
    __syncthreads();

    float acc[8][4];
#pragma unroll
    for (int nt = 0; nt < 8; nt++)
#pragma unroll
        for (int i = 0; i < 4; i++) acc[nt][i] = 0.f;

    const unsigned* sAu = (const unsigned*)sA;
    for (int ks = 0; ks < 16; ks++) {
        unsigned a[4];
        int R = wm * 16 + gid, col = ks * 8 + tg;
        a[0] = sAu[R * 132 + col];
        a[1] = sAu[(R + 8) * 132 + col];
        a[2] = sAu[R * 132 + col + 4];
        a[3] = sAu[(R + 8) * 132 + col + 4];
#pragma unroll
        for (int nt = 0; nt < 8; nt++) {
            int Cc = wn * 64 + nt * 8 + gid;
            unsigned b0 = sB[(ks * 8 + tg) * 132 + Cc];
            unsigned b1 = sB[(ks * 8 + tg + 4) * 132 + Cc];
            mma_tf32(acc[nt], a, b0, b1);
        }
    }

#pragma unroll
    for (int nt = 0; nt < 8; nt++)
#pragma unroll
        for (int p = 0; p < 2; p++) {
            int row = wm * 16 + gid + p * 8;
            int gm = m0 + row;
            if (gm < M) {
                int col = wn * 64 + nt * 8 + 2 * tg;
                float2 v;
                v.x = acc[nt][p * 2]     + __ldg(bias + n0 + col);
                v.y = acc[nt][p * 2 + 1] + __ldg(bias + n0 + col + 1);
                if (do_relu) { v.x = fmaxf(v.x, 0.f); v.y = fmaxf(v.y, 0.f); }
                *(float2*)(C + (size_t)gm * Ntot + n0 + col) = v;
            }
        }
}

// ---------------- edge kernel: hidden = relu(P[src] + eattr@W1e); m = hidden@W2+b2
// BM=128 edges, double-buffered cp.async gather, v4 red scatter.
#define OFF_W2  0
#define OFF_W1E (128 * 132)
#define OFF_A   (OFF_W1E + 16 * 132)             // 2 bufs of 128*132
#define OFF_E   (OFF_A + 2 * 128 * 132)          // 2 bufs of 128*20
#define EDGE_WORDS (OFF_E + 2 * 128 * 20)
#define EDGE_SMEM (EDGE_WORDS * 4)               // 231680 B

__global__ void __launch_bounds__(256, 1)
edge_kernel(const float* __restrict__ eattr,
            const int* __restrict__ src,
            const int* __restrict__ dst,
            const float* __restrict__ W1e,   // [16,128]
            const float* __restrict__ W2,    // [128,128]
            const float* __restrict__ b2) {
    extern __shared__ unsigned smu[];
    unsigned* sW2  = smu + OFF_W2;
    unsigned* sW1e = smu + OFF_W1E;
    float*    smf  = (float*)smu;
    __shared__ float sB2[128];
    uint32_t smem_u32 = (uint32_t)__cvta_generic_to_shared(smu);

    int tid = threadIdx.x, lane = tid & 31, wid = tid >> 5;
    int wm = wid & 3, wn = wid >> 2, gid = lane >> 2, tg = lane & 3;
    int r2 = tid >> 1, half = tid & 1;

    // prologue: gather tile blockIdx.x into buf 0
    {
        int e0 = blockIdx.x * 128;
        int s = __ldg(src + e0 + r2);
        const float* pr = g_p + (size_t)s * HID + half * 64;
        uint32_t sa = smem_u32 + (OFF_A + r2 * 132 + half * 64) * 4;
#pragma unroll
        for (int k = 0; k < 16; k++) cp16(sa + k * 16, pr + k * 4);
        const float* er = eattr + (size_t)(e0 + r2) * EDGE_DIM + half * 8;
        uint32_t se = smem_u32 + (OFF_E + r2 * 20 + half * 8) * 4;
        cp16(se, er); cp16(se + 16, er + 4);
        asm volatile("cp.async.commit_group;");
    }
    // stage weights (overlaps with in-flight gather)
    for (int i = tid; i < HID * HID; i += 256)
        sW2[(i >> 7) * 132 + (i & 127)] = f2tf(__ldg(W2 + i));
    for (int i = tid; i < EDGE_DIM * HID; i += 256)
        sW1e[(i >> 7) * 132 + (i & 127)] = f2tf(__ldg(W1e + i));
    if (tid < 128) sB2[tid] = b2[tid];

    const int ntiles = N_EDGES / 128;  // 6250
    int buf = 0;
    for (int t = blockIdx.x; t < ntiles; t += gridDim.x) {
        int tn = t + gridDim.x;
        if (tn < ntiles) {  // prefetch next tile into buf^1
            int e0n = tn * 128;
            int s = __ldg(src + e0n + r2);
            const float* pr = g_p + (size_t)s * HID + half * 64;
            uint32_t sa = smem_u32 + (OFF_A + (buf ^ 1) * (128 * 132) + r2 * 132 + half * 64) * 4;
#pragma unroll
            for (int k = 0; k < 16; k++) cp16(sa + k * 16, pr + k * 4);
            const float* er = eattr + (size_t)(e0n + r2) * EDGE_DIM + half * 8;
            uint32_t se = smem_u32 + (OFF_E + (buf ^ 1) * (128 * 20) + r2 * 20 + half * 8) * 4;
            cp16(se, er); cp16(se + 16, er + 4);
        }
        asm volatile("cp.async.commit_group;");
        asm volatile("cp.async.wait_group 1;");
        __syncthreads();

        float*    sAf = smf + OFF_A + buf * (128 * 132);
        unsigned* sAu = (unsigned*)sAf;
        unsigned* sEu = smu + OFF_E + buf * (128 * 20);
        int e0 = t * 128;

        // ---- accumulator init from P[src] (fp32), then K=16 MMA with eattr
        float acc[2][8][4];
#pragma unroll
        for (int mt = 0; mt < 2; mt++) {
            int R = wm * 32 + mt * 16 + gid;
#pragma unroll
            for (int nt = 0; nt < 8; nt++) {
                int Cc = wn * 64 + nt * 8 + 2 * tg;
                float2 v0 = *(float2*)(sAf + R * 132 + Cc);
                float2 v1 = *(float2*)(sAf + (R + 8) * 132 + Cc);
                acc[mt][nt][0] = v0.x; acc[mt][nt][1] = v0.y;
                acc[mt][nt][2] = v1.x; acc[mt][nt][3] = v1.y;
            }
        }
#pragma unroll
        for (int ks = 0; ks < 2; ks++) {
            unsigned a[2][4];
#pragma unroll
            for (int mt = 0; mt < 2; mt++) {
                int R = wm * 32 + mt * 16 + gid, col = ks * 8 + tg;
                a[mt][0] = sEu[R * 20 + col];
                a[mt][1] = sEu[(R + 8) * 20 + col];
                a[mt][2] = sEu[R * 20 + col + 4];
                a[mt][3] = sEu[(R + 8) * 20 + col + 4];
            }
#pragma unroll
            for (int nt = 0; nt < 8; nt++) {
                int Cc = wn * 64 + nt * 8 + gid;
                unsigned b0 = sW1e[(ks * 8 + tg) * 132 + Cc];
                unsigned b1 = sW1e[(ks * 8 + tg + 4) * 132 + Cc];
                mma_tf32(acc[0][nt], a[0], b0, b1);
                mma_tf32(acc[1][nt], a[1], b0, b1);
            }
        }
        // relu, write hidden into own warp region of sA[buf] (no cross-warp hazard)
#pragma unroll
        for (int mt = 0; mt < 2; mt++)
#pragma unroll
            for (int nt = 0; nt < 8; nt++)
#pragma unroll
                for (int i = 0; i < 4; i++) {
                    int row = wm * 32 + mt * 16 + gid + ((i >> 1) << 3);
                    int col = wn * 64 + nt * 8 + 2 * tg + (i & 1);
                    sAu[row * 132 + col] = f2tf(fmaxf(acc[mt][nt][i], 0.f));
                }
        __syncthreads();

        // ---- stage 2: m = hidden @ W2, K=128
#pragma unroll
        for (int mt = 0; mt < 2; mt++)
#pragma unroll
            for (int nt = 0; nt < 8; nt++)
#pragma unroll
                for (int i = 0; i < 4; i++) acc[mt][nt][i] = 0.f;
        for (int ks = 0; ks < 16; ks++) {
            unsigned a[2][4];
#pragma unroll
            for (int mt = 0; mt < 2; mt++) {
                int R = wm * 32 + mt * 16 + gid, col = ks * 8 + tg;
                a[mt][0] = sAu[R * 132 + col];
                a[mt][1] = sAu[(R + 8) * 132 + col];
                a[mt][2] = sAu[R * 132 + col + 4];
                a[mt][3] = sAu[(R + 8) * 132 + col + 4];
            }
#pragma unroll
            for (int nt = 0; nt < 8; nt++) {
                int Cc = wn * 64 + nt * 8 + gid;
                unsigned b0 = sW2[(ks * 8 + tg) * 132 + Cc];
                unsigned b1 = sW2[(ks * 8 + tg + 4) * 132 + Cc];
                mma_tf32(acc[0][nt], a[0], b0, b1);
                mma_tf32(acc[1][nt], a[1], b0, b1);
            }
        }
        __syncthreads();  // all warps done reading hidden

        // stage outputs (+b2) into sA[buf]
#pragma unroll
        for (int mt = 0; mt < 2; mt++)
#pragma unroll
            for (int nt = 0; nt < 8; nt++)
#pragma unroll
                for (int i = 0; i < 4; i++) {
                    int row = wm * 32 + mt * 16 + gid + ((i >> 1) << 3);
                    int col = wn * 64 + nt * 8 + 2 * tg + (i & 1);
                    sAf[row * 132 + col] = acc[mt][nt][i] + sB2[col];
                }
        __syncthreads();

        // coalesced v4 scatter-add: 2 threads per edge row
        {
            int d = __ldg(dst + e0 + r2);
            float* gp = g_agg + (size_t)d * HID + half * 64;
            const float4* sp = (const float4*)(sAf + r2 * 132 + half * 64);
#pragma unroll
            for (int k = 0; k < 16; k++) red4(gp + k * 4, sp[k]);
        }
        __syncthreads();
        buf ^= 1;
    }
}

// ---------------- GRU gates + BN + residual (elementwise) ----------------
__global__ void gru_epi_kernel(const float* __restrict__ gamma,
                               const float* __restrict__ beta,
                               const float* __restrict__ mean,
                               const float* __restrict__ var) {
    int idx = blockIdx.x * blockDim.x + threadIdx.x;
    if (idx >= N_NODES * HID) return;
    int n = idx >> 7, j = idx & 127;
    const float* gi = g_gi + (size_t)n * 384;
    const float* gh = g_gh + (size_t)n * 384;
    float ir = gi[j], iz = gi[128 + j], inn = gi[256 + j];
    float hr = gh[j], hz = gh[128 + j], hn  = gh[256 + j];
    float h = g_h[idx];
    float r = 1.f / (1.f + __expf(-(ir + hr)));
    float z = 1.f / (1.f + __expf(-(iz + hz)));
    float nn = tanhf(inn + r * hn);
    float hnew = (1.f - z) * nn + z * h;
    float bn = (hnew - mean[j]) * rsqrtf(var[j] + BN_EPS) * gamma[j] + beta[j];
    g_h[idx] = h + bn;
}

// ---------------- readout ----------------
__global__ void readout_acc_kernel(const int* __restrict__ batch) {
    int idx = blockIdx.x * blockDim.x + threadIdx.x;
    if (idx >= N_NODES * HID) return;
    int n = idx >> 7, j = idx & 127;
    int b = batch[n];
    float v = g_h[idx];
    atomicAdd(&g_rsum[b * HID + j], v);
    atomicMax(&g_rmax[b * HID + j], fenc(v));
    if (j == 0) atomicAdd(&g_rcnt[b], 1);
}
__global__ void readout_final_kernel(const float* __restrict__ roW,
                                     const float* __restrict__ roB,
                                     float* __restrict__ out) {
    __shared__ float s[2 * HID];
    int g = blockIdx.x, j = threadIdx.x;
    int cnt = g_rcnt[g];
    float mv = g_rsum[g * HID + j] / fmaxf((float)cnt, 1.f);
    float xv = (cnt > 0) ? fdec(g_rmax[g * HID + j]) : 0.f;
    s[j] = mv;
    s[HID + j] = xv;
    __syncthreads();
    float acc = roB[j];
    for (int k = 0; k < 2 * HID; k++) acc += s[k] * roW[k * HID + j];
    out[g * HID + j] = fmaxf(acc, 0.f);
}

// ---------------- launch ----------------
extern "C" void kernel_launch(void* const* d_in, const int* in_sizes, int n_in,
                              void* d_out, int out_size) {
    int base = (in_sizes[4] <= 2) ? 5 : 4;
    const float* x     = (const float*)d_in[0];
    const int*   eidx  = (const int*)d_in[1];
    const float* eattr = (const float*)d_in[2];
    const int*   batch = (const int*)d_in[3];
    const float* linW  = (const float*)d_in[base + 0];
    const float* linB  = (const float*)d_in[base + 1];
    const float* w1    = (const float*)d_in[base + 2];
    const float* b1    = (const float*)d_in[base + 3];
    const float* w2    = (const float*)d_in[base + 4];
    const float* b2    = (const float*)d_in[base + 5];
    const float* bng   = (const float*)d_in[base + 6];
    const float* bnb   = (const float*)d_in[base + 7];
    const float* bnm   = (const float*)d_in[base + 8];
    const float* bnv   = (const float*)d_in[base + 9];
    const float* wih   = (const float*)d_in[base + 10];
    const float* whh   = (const float*)d_in[base + 11];
    const float* bih   = (const float*)d_in[base + 12];
    const float* bhh   = (const float*)d_in[base + 13];
    const float* roW   = (const float*)d_in[base + 14];
    const float* roB   = (const float*)d_in[base + 15];
    float* out = (float*)d_out;

    cudaFuncSetAttribute(dense_mma,  cudaFuncAttributeMaxDynamicSharedMemorySize, DEN_SMEM);
    cudaFuncSetAttribute(edge_kernel, cudaFuncAttributeMaxDynamicSharedMemorySize, EDGE_SMEM);

    float *hp, *aggp, *pp, *gip, *ghp, *wihTp, *whhTp;
    cudaGetSymbolAddress((void**)&hp,    g_h);
    cudaGetSymbolAddress((void**)&aggp,  g_agg);
    cudaGetSymbolAddress((void**)&pp,    g_p);
    cudaGetSymbolAddress((void**)&gip,   g_gi);
    cudaGetSymbolAddress((void**)&ghp,   g_gh);
    cudaGetSymbolAddress((void**)&wihTp, g_wihT);
    cudaGetSymbolAddress((void**)&whhTp, g_whhT);

    const int MT = (N_NODES + 63) / 64;  // 782

    // h = relu(x @ linW + linB)
    dense_mma<<<dim3(MT, 1), 256, DEN_SMEM>>>(x, linW, linB, hp, N_NODES, 128, 1);
    transpose_w_kernel<<<(N_LAYERS * 3 * HID * HID + 255) / 256, 256>>>(wih, whh);

    for (int l = 0; l < N_LAYERS; l++) {
        zero_agg_kernel<<<(N_NODES * HID / 4 + 255) / 256, 256>>>();
        // P = h @ W1h + b1   (W1h = first 128 rows of W1[l])
        dense_mma<<<dim3(MT, 1), 256, DEN_SMEM>>>(
            hp, w1 + (size_t)l * 144 * 128, b1 + l * 128, pp, N_NODES, 128, 0);
        // per-edge: hidden = relu(P[src] + e@W1e); m = hidden@W2+b2; scatter
        edge_kernel<<<148, 256, EDGE_SMEM>>>(
            eattr, eidx, eidx + N_EDGES,
            w1 + (size_t)l * 144 * 128 + 128 * 128,
            w2 + (size_t)l * 128 * 128, b2 + l * 128);
        // gi = agg @ wihT + bih ; gh = h @ whhT + bhh
        dense_mma<<<dim3(MT, 3), 256, DEN_SMEM>>>(
            aggp, wihTp + (size_t)l * 128 * 384, bih + l * 384, gip, N_NODES, 384, 0);
        dense_mma<<<dim3(MT, 3), 256, DEN_SMEM>>>(
            hp, whhTp + (size_t)l * 128 * 384, bhh + l * 384, ghp, N_NODES, 384, 0);
        gru_epi_kernel<<<(N_NODES * HID + 255) / 256, 256>>>(
            bng + l * 128, bnb + l * 128, bnm + l * 128, bnv + l * 128);
    }

    zero_readout_kernel<<<(N_GRAPHS * HID + 255) / 256, 256>>>();
    readout_acc_kernel<<<(N_NODES * HID + 255) / 256, 256>>>(batch);
    readout_final_kernel<<<N_GRAPHS, HID>>>(roW, roB, out);
}

// round 5
// speedup vs baseline: 5.8198x; 1.1539x over previous
#include <cuda_runtime.h>
#include <math.h>
#include <stdint.h>

#define N_NODES   50000
#define N_EDGES   800000
#define IN_DIM    128
#define EDGE_DIM  16
#define HID       128
#define N_LAYERS  3
#define N_GRAPHS  256
#define BN_EPS    1e-5f

// ---------------- scratch (static __device__, no allocation) ----------------
__device__ float    g_h[N_NODES * HID];
__device__ float    g_agg[N_NODES * HID];
__device__ float    g_p[N_NODES * HID];            // P = h@W1h + b1
__device__ float    g_gi[N_NODES * 3 * HID];
__device__ float    g_gh[N_NODES * 3 * HID];
__device__ float    g_wihT[N_LAYERS * HID * 3 * HID];  // [l][k][o]
__device__ float    g_whhT[N_LAYERS * HID * 3 * HID];
__device__ float    g_rsum[N_GRAPHS * HID];
__device__ unsigned g_rmax[N_GRAPHS * HID];
__device__ int      g_rcnt[N_GRAPHS];

// ---------------- helpers ----------------
__device__ __forceinline__ unsigned fenc(float f) {
    unsigned u = __float_as_uint(f);
    return (u & 0x80000000u) ? ~u : (u | 0x80000000u);
}
__device__ __forceinline__ float fdec(unsigned k) {
    return __uint_as_float((k & 0x80000000u) ? (k & 0x7fffffffu) : ~k);
}
__device__ __forceinline__ unsigned f2tf(float f) {
    unsigned u;
    asm("cvt.rna.tf32.f32 %0, %1;" : "=r"(u) : "f"(f));
    return u;
}
__device__ __forceinline__ void mma_tf32(float* c, const unsigned* a,
                                         unsigned b0, unsigned b1) {
    asm volatile(
        "mma.sync.aligned.m16n8k8.row.col.f32.tf32.tf32.f32 "
        "{%0,%1,%2,%3}, {%4,%5,%6,%7}, {%8,%9}, {%0,%1,%2,%3};"
        : "+f"(c[0]), "+f"(c[1]), "+f"(c[2]), "+f"(c[3])
        : "r"(a[0]), "r"(a[1]), "r"(a[2]), "r"(a[3]), "r"(b0), "r"(b1));
}
__device__ __forceinline__ void cp16(uint32_t s, const void* g) {
    asm volatile("cp.async.cg.shared.global [%0], [%1], 16;" :: "r"(s), "l"(g));
}
__device__ __forceinline__ void red2(float* p, float a, float b) {
    asm volatile("red.global.add.v2.f32 [%0], {%1,%2};"
                 :: "l"(p), "f"(a), "f"(b) : "memory");
}

// ---------------- zero / setup ----------------
__global__ void zero_agg_kernel() {
    int i = blockIdx.x * blockDim.x + threadIdx.x;
    if (i < (N_NODES * HID) / 4)
        ((float4*)g_agg)[i] = make_float4(0.f, 0.f, 0.f, 0.f);
}
__global__ void zero_readout_kernel() {
    int i = blockIdx.x * blockDim.x + threadIdx.x;
    if (i < N_GRAPHS * HID) { g_rsum[i] = 0.f; g_rmax[i] = 0u; }
    if (i < N_GRAPHS) g_rcnt[i] = 0;
}
__global__ void transpose_w_kernel(const float* __restrict__ wih,
                                   const float* __restrict__ whh) {
    int idx = blockIdx.x * blockDim.x + threadIdx.x;
    const int per_layer = 3 * HID * HID;
    if (idx >= N_LAYERS * per_layer) return;
    int l = idx / per_layer;
    int r = idx - l * per_layer;
    int o = r / HID;
    int k = r - o * HID;
    g_wihT[l * per_layer + k * (3 * HID) + o] = wih[idx];
    g_whhT[l * per_layer + k * (3 * HID) + o] = whh[idx];
}

// ---------------- persistent dense tf32 GEMM ----------------
// Weight slab (128 x 128 cols at n0) resident in SMEM; CTA grid-strides over
// BM=128 M-tiles with cp.async double-buffered A. Two (A,B,C) pairs so gi and
// gh run in one launch: slab < nslabA -> pair a, else pair b.
#define PD_SMEM ((128 * 132 + 2 * 128 * 132) * 4)   // 202752 B
__global__ void __launch_bounds__(256, 1)
pdense(const float* __restrict__ Aa, const float* __restrict__ Ba,
       const float* __restrict__ biasa, float* __restrict__ Ca,
       const float* __restrict__ Ab, const float* __restrict__ Bb,
       const float* __restrict__ biasb, float* __restrict__ Cb,
       int M, int nB, int nC, int nslabA, int relu) {
    extern __shared__ unsigned psm[];
    unsigned* sB = psm;                        // 128 x 132 tf32
    float*    sA = (float*)(psm + 128 * 132);  // 2 x (128 x 132) fp32
    int slab = blockIdx.y;
    const float *A, *B, *bias; float* C; int n0;
    if (slab < nslabA) { A = Aa; B = Ba; bias = biasa; C = Ca; n0 = slab * 128; }
    else { A = Ab; B = Bb; bias = biasb; C = Cb; n0 = (slab - nslabA) * 128; }

    int tid = threadIdx.x, lane = tid & 31, wid = tid >> 5;
    int wm = wid & 3, wn = wid >> 2, gid = lane >> 2, tg = lane & 3;
    int r2 = tid >> 1, half = tid & 1;
    uint32_t sa_u32 = (uint32_t)__cvta_generic_to_shared(sA);

    const int tiles = (M + 127) >> 7;
    // prologue: tile blockIdx.x -> buf 0
    {
        int gm = blockIdx.x * 128 + r2; if (gm >= M) gm = M - 1;
        const float* ar = A + (size_t)gm * 128 + half * 64;
        uint32_t sa = sa_u32 + (r2 * 132 + half * 64) * 4;
#pragma unroll
        for (int k = 0; k < 16; k++) cp16(sa + k * 16, ar + k * 4);
        asm volatile("cp.async.commit_group;");
    }
    // stage weight slab (overlaps in-flight A load)
    for (int i = tid; i < 128 * 128; i += 256)
        sB[(i >> 7) * 132 + (i & 127)] =
            f2tf(__ldg(B + (size_t)(i >> 7) * nB + n0 + (i & 127)));

    int buf = 0;
    for (int t = blockIdx.x; t < tiles; t += gridDim.x) {
        int tn = t + gridDim.x;
        if (tn < tiles) {
            int gm = tn * 128 + r2; if (gm >= M) gm = M - 1;
            const float* ar = A + (size_t)gm * 128 + half * 64;
            uint32_t sa = sa_u32 + ((buf ^ 1) * 128 * 132 + r2 * 132 + half * 64) * 4;
#pragma unroll
            for (int k = 0; k < 16; k++) cp16(sa + k * 16, ar + k * 4);
        }
        asm volatile("cp.async.commit_group;");
        asm volatile("cp.async.wait_group 1;");
        __syncthreads();

        const unsigned* sAu = (const unsigned*)(sA + buf * 128 * 132);
        float acc[2][8][4];
#pragma unroll
        for (int mt = 0; mt < 2; mt++)
#pragma unroll
            for (int nt = 0; nt < 8; nt++)
#pragma unroll
                for (int i = 0; i < 4; i++) acc[mt][nt][i] = 0.f;

        for (int ks = 0; ks < 16; ks++) {
            unsigned a[2][4];
#pragma unroll
            for (int mt = 0; mt < 2; mt++) {
                int R = wm * 32 + mt * 16 + gid, col = ks * 8 + tg;
                a[mt][0] = sAu[R * 132 + col];
                a[mt][1] = sAu[(R + 8) * 132 + col];
                a[mt][2] = sAu[R * 132 + col + 4];
                a[mt][3] = sAu[(R + 8) * 132 + col + 4];
            }
#pragma unroll
            for (int nt = 0; nt < 8; nt++) {
                int Cc = wn * 64 + nt * 8 + gid;
                unsigned b0 = sB[(ks * 8 + tg) * 132 + Cc];
                unsigned b1 = sB[(ks * 8 + tg + 4) * 132 + Cc];
                mma_tf32(acc[0][nt], a[0], b0, b1);
                mma_tf32(acc[1][nt], a[1], b0, b1);
            }
        }

        int m0 = t * 128;
#pragma unroll
        for (int mt = 0; mt < 2; mt++)
#pragma unroll
            for (int nt = 0; nt < 8; nt++)
#pragma unroll
                for (int p = 0; p < 2; p++) {
                    int gm = m0 + wm * 32 + mt * 16 + gid + p * 8;
                    if (gm < M) {
                        int col = wn * 64 + nt * 8 + 2 * tg;
                        float2 v;
                        v.x = acc[mt][nt][p * 2]     + __ldg(bias + n0 + col);
                        v.y = acc[mt][nt][p * 2 + 1] + __ldg(bias + n0 + col + 1);
                        if (relu) { v.x = fmaxf(v.x, 0.f); v.y = fmaxf(v.y, 0.f); }
                        *(float2*)(C + (size_t)gm * nC + n0 + col) = v;
                    }
                }
        __syncthreads();
        buf ^= 1;
    }
}

// ---------------- edge kernel ----------------
// hidden = relu(P[src] + eattr@W1e); m = hidden@W2 + b2; red.v2 scatter.
#define OFF_W2  0
#define OFF_W1E (128 * 132)
#define OFF_A   (OFF_W1E + 16 * 132)
#define OFF_E   (OFF_A + 2 * 128 * 132)
#define EDGE_WORDS (OFF_E + 2 * 128 * 20)
#define EDGE_SMEM (EDGE_WORDS * 4)               // 231680 B

__global__ void __launch_bounds__(256, 1)
edge_kernel(const float* __restrict__ eattr,
            const int* __restrict__ src,
            const int* __restrict__ dst,
            const float* __restrict__ W1e,
            const float* __restrict__ W2,
            const float* __restrict__ b2) {
    extern __shared__ unsigned smu[];
    unsigned* sW2  = smu + OFF_W2;
    unsigned* sW1e = smu + OFF_W1E;
    float*    smf  = (float*)smu;
    __shared__ float sB2[128];
    uint32_t smem_u32 = (uint32_t)__cvta_generic_to_shared(smu);

    int tid = threadIdx.x, lane = tid & 31, wid = tid >> 5;
    int wm = wid & 3, wn = wid >> 2, gid = lane >> 2, tg = lane & 3;
    int r2 = tid >> 1, half = tid & 1;

    {
        int e0 = blockIdx.x * 128;
        int s = __ldg(src + e0 + r2);
        const float* pr = g_p + (size_t)s * HID + half * 64;
        uint32_t sa = smem_u32 + (OFF_A + r2 * 132 + half * 64) * 4;
#pragma unroll
        for (int k = 0; k < 16; k++) cp16(sa + k * 16, pr + k * 4);
        const float* er = eattr + (size_t)(e0 + r2) * EDGE_DIM + half * 8;
        uint32_t se = smem_u32 + (OFF_E + r2 * 20 + half * 8) * 4;
        cp16(se, er); cp16(se + 16, er + 4);
        asm volatile("cp.async.commit_group;");
    }
    for (int i = tid; i < HID * HID; i += 256)
        sW2[(i >> 7) * 132 + (i & 127)] = f2tf(__ldg(W2 + i));
    for (int i = tid; i < EDGE_DIM * HID; i += 256)
        sW1e[(i >> 7) * 132 + (i & 127)] = f2tf(__ldg(W1e + i));
    if (tid < 128) sB2[tid] = b2[tid];

    const int ntiles = N_EDGES / 128;  // 6250
    int buf = 0;
    for (int t = blockIdx.x; t < ntiles; t += gridDim.x) {
        int tn = t + gridDim.x;
        if (tn < ntiles) {
            int e0n = tn * 128;
            int s = __ldg(src + e0n + r2);
            const float* pr = g_p + (size_t)s * HID + half * 64;
            uint32_t sa = smem_u32 + (OFF_A + (buf ^ 1) * (128 * 132) + r2 * 132 + half * 64) * 4;
#pragma unroll
            for (int k = 0; k < 16; k++) cp16(sa + k * 16, pr + k * 4);
            const float* er = eattr + (size_t)(e0n + r2) * EDGE_DIM + half * 8;
            uint32_t se = smem_u32 + (OFF_E + (buf ^ 1) * (128 * 20) + r2 * 20 + half * 8) * 4;
            cp16(se, er); cp16(se + 16, er + 4);
        }
        asm volatile("cp.async.commit_group;");
        asm volatile("cp.async.wait_group 1;");
        __syncthreads();

        float*    sAf = smf + OFF_A + buf * (128 * 132);
        unsigned* sAu = (unsigned*)sAf;
        unsigned* sEu = smu + OFF_E + buf * (128 * 20);
        int e0 = t * 128;

        // stage 1: acc = P[src] (fp32) + eattr@W1e (K=16), relu -> hidden
        float acc[2][8][4];
#pragma unroll
        for (int mt = 0; mt < 2; mt++) {
            int R = wm * 32 + mt * 16 + gid;
#pragma unroll
            for (int nt = 0; nt < 8; nt++) {
                int Cc = wn * 64 + nt * 8 + 2 * tg;
                float2 v0 = *(float2*)(sAf + R * 132 + Cc);
                float2 v1 = *(float2*)(sAf + (R + 8) * 132 + Cc);
                acc[mt][nt][0] = v0.x; acc[mt][nt][1] = v0.y;
                acc[mt][nt][2] = v1.x; acc[mt][nt][3] = v1.y;
            }
        }
#pragma unroll
        for (int ks = 0; ks < 2; ks++) {
            unsigned a[2][4];
#pragma unroll
            for (int mt = 0; mt < 2; mt++) {
                int R = wm * 32 + mt * 16 + gid, col = ks * 8 + tg;
                a[mt][0] = sEu[R * 20 + col];
                a[mt][1] = sEu[(R + 8) * 20 + col];
                a[mt][2] = sEu[R * 20 + col + 4];
                a[mt][3] = sEu[(R + 8) * 20 + col + 4];
            }
#pragma unroll
            for (int nt = 0; nt < 8; nt++) {
                int Cc = wn * 64 + nt * 8 + gid;
                unsigned b0 = sW1e[(ks * 8 + tg) * 132 + Cc];
                unsigned b1 = sW1e[(ks * 8 + tg + 4) * 132 + Cc];
                mma_tf32(acc[0][nt], a[0], b0, b1);
                mma_tf32(acc[1][nt], a[1], b0, b1);
            }
        }
#pragma unroll
        for (int mt = 0; mt < 2; mt++)
#pragma unroll
            for (int nt = 0; nt < 8; nt++)
#pragma unroll
                for (int i = 0; i < 4; i++) {
                    int row = wm * 32 + mt * 16 + gid + ((i >> 1) << 3);
                    int col = wn * 64 + nt * 8 + 2 * tg + (i & 1);
                    sAu[row * 132 + col] = f2tf(fmaxf(acc[mt][nt][i], 0.f));
                }
        __syncthreads();

        // stage 2: m = hidden @ W2, K=128
#pragma unroll
        for (int mt = 0; mt < 2; mt++)
#pragma unroll
            for (int nt = 0; nt < 8; nt++)
#pragma unroll
                for (int i = 0; i < 4; i++) acc[mt][nt][i] = 0.f;
        for (int ks = 0; ks < 16; ks++) {
            unsigned a[2][4];
#pragma unroll
            for (int mt = 0; mt < 2; mt++) {
                int R = wm * 32 + mt * 16 + gid, col = ks * 8 + tg;
                a[mt][0] = sAu[R * 132 + col];
                a[mt][1] = sAu[(R + 8) * 132 + col];
                a[mt][2] = sAu[R * 132 + col + 4];
                a[mt][3] = sAu[(R + 8) * 132 + col + 4];
            }
#pragma unroll
            for (int nt = 0; nt < 8; nt++) {
                int Cc = wn * 64 + nt * 8 + gid;
                unsigned b0 = sW2[(ks * 8 + tg) * 132 + Cc];
                unsigned b1 = sW2[(ks * 8 + tg + 4) * 132 + Cc];
                mma_tf32(acc[0][nt], a[0], b0, b1);
                mma_tf32(acc[1][nt], a[1], b0, b1);
            }
        }
        __syncthreads();  // all warps done with sAu before next prefetch reuses it

        // epilogue: direct red.v2 from registers (no SMEM round trip)
        int dr[2][2];
#pragma unroll
        for (int mt = 0; mt < 2; mt++) {
            dr[mt][0] = __ldg(dst + e0 + wm * 32 + mt * 16 + gid);
            dr[mt][1] = __ldg(dst + e0 + wm * 32 + mt * 16 + gid + 8);
        }
#pragma unroll
        for (int mt = 0; mt < 2; mt++)
#pragma unroll
            for (int nt = 0; nt < 8; nt++) {
                int col = wn * 64 + nt * 8 + 2 * tg;
                float bb0 = sB2[col], bb1 = sB2[col + 1];
                red2(&g_agg[(size_t)dr[mt][0] * HID + col],
                     acc[mt][nt][0] + bb0, acc[mt][nt][1] + bb1);
                red2(&g_agg[(size_t)dr[mt][1] * HID + col],
                     acc[mt][nt][2] + bb0, acc[mt][nt][3] + bb1);
            }
        buf ^= 1;
    }
}

// ---------------- GRU gates + BN + residual (+ zero agg for next layer) ----
__global__ void gru_epi_kernel(const float* __restrict__ gamma,
                               const float* __restrict__ beta,
                               const float* __restrict__ mean,
                               const float* __restrict__ var) {
    int idx = blockIdx.x * blockDim.x + threadIdx.x;
    if (idx >= N_NODES * HID) return;
    int n = idx >> 7, j = idx & 127;
    const float* gi = g_gi + (size_t)n * 384;
    const float* gh = g_gh + (size_t)n * 384;
    float ir = gi[j], iz = gi[128 + j], inn = gi[256 + j];
    float hr = gh[j], hz = gh[128 + j], hn  = gh[256 + j];
    float h = g_h[idx];
    float r = 1.f / (1.f + __expf(-(ir + hr)));
    float z = 1.f / (1.f + __expf(-(iz + hz)));
    float nn = tanhf(inn + r * hn);
    float hnew = (1.f - z) * nn + z * h;
    float bn = (hnew - mean[j]) * rsqrtf(var[j] + BN_EPS) * gamma[j] + beta[j];
    g_h[idx] = h + bn;
    g_agg[idx] = 0.f;   // pre-zero aggregation buffer for next layer
}

// ---------------- readout: run-length segmented reduction ----------------
__global__ void readout_acc_kernel(const int* __restrict__ batch) {
    __shared__ int sb[128];
    int j = threadIdx.x;
    int nBeg = blockIdx.x * 128;
    int cnt = min(128, N_NODES - nBeg);
    sb[j] = (j < cnt) ? __ldg(batch + nBeg + j) : -1;
    __syncthreads();
    int curb = sb[0];
    float s = 0.f; unsigned mx = 0u; int c = 0;
    for (int i = 0; i < cnt; i++) {
        int b = sb[i];
        float v = g_h[(size_t)(nBeg + i) * HID + j];
        if (b != curb) {
            atomicAdd(&g_rsum[curb * HID + j], s);
            atomicMax(&g_rmax[curb * HID + j], mx);
            if (j == 0) atomicAdd(&g_rcnt[curb], c);
            s = 0.f; mx = 0u; c = 0; curb = b;
        }
        s += v; mx = max(mx, fenc(v)); c++;
    }
    if (c > 0) {
        atomicAdd(&g_rsum[curb * HID + j], s);
        atomicMax(&g_rmax[curb * HID + j], mx);
        if (j == 0) atomicAdd(&g_rcnt[curb], c);
    }
}
__global__ void readout_final_kernel(const float* __restrict__ roW,
                                     const float* __restrict__ roB,
                                     float* __restrict__ out) {
    __shared__ float s[2 * HID];
    int g = blockIdx.x, j = threadIdx.x;
    int cnt = g_rcnt[g];
    float mv = g_rsum[g * HID + j] / fmaxf((float)cnt, 1.f);
    float xv = (cnt > 0) ? fdec(g_rmax[g * HID + j]) : 0.f;
    s[j] = mv;
    s[HID + j] = xv;
    __syncthreads();
    float acc = roB[j];
    for (int k = 0; k < 2 * HID; k++) acc += s[k] * roW[k * HID + j];
    out[g * HID + j] = fmaxf(acc, 0.f);
}

// ---------------- launch ----------------
extern "C" void kernel_launch(void* const* d_in, const int* in_sizes, int n_in,
                              void* d_out, int out_size) {
    int base = (in_sizes[4] <= 2) ? 5 : 4;
    const float* x     = (const float*)d_in[0];
    const int*   eidx  = (const int*)d_in[1];
    const float* eattr = (const float*)d_in[2];
    const int*   batch = (const int*)d_in[3];
    const float* linW  = (const float*)d_in[base + 0];
    const float* linB  = (const float*)d_in[base + 1];
    const float* w1    = (const float*)d_in[base + 2];
    const float* b1    = (const float*)d_in[base + 3];
    const float* w2    = (const float*)d_in[base + 4];
    const float* b2    = (const float*)d_in[base + 5];
    const float* bng   = (const float*)d_in[base + 6];
    const float* bnb   = (const float*)d_in[base + 7];
    const float* bnm   = (const float*)d_in[base + 8];
    const float* bnv   = (const float*)d_in[base + 9];
    const float* wih   = (const float*)d_in[base + 10];
    const float* whh   = (const float*)d_in[base + 11];
    const float* bih   = (const float*)d_in[base + 12];
    const float* bhh   = (const float*)d_in[base + 13];
    const float* roW   = (const float*)d_in[base + 14];
    const float* roB   = (const float*)d_in[base + 15];
    float* out = (float*)d_out;

    cudaFuncSetAttribute(pdense,      cudaFuncAttributeMaxDynamicSharedMemorySize, PD_SMEM);
    cudaFuncSetAttribute(edge_kernel, cudaFuncAttributeMaxDynamicSharedMemorySize, EDGE_SMEM);

    float *hp, *aggp, *pp, *gip, *ghp, *wihTp, *whhTp;
    cudaGetSymbolAddress((void**)&hp,    g_h);
    cudaGetSymbolAddress((void**)&aggp,  g_agg);
    cudaGetSymbolAddress((void**)&pp,    g_p);
    cudaGetSymbolAddress((void**)&gip,   g_gi);
    cudaGetSymbolAddress((void**)&ghp,   g_gh);
    cudaGetSymbolAddress((void**)&wihTp, g_wihT);
    cudaGetSymbolAddress((void**)&whhTp, g_whhT);

    // h = relu(x @ linW + linB)
    pdense<<<dim3(148, 1), 256, PD_SMEM>>>(x, linW, linB, hp,
                                           x, linW, linB, hp,
                                           N_NODES, 128, 128, 1, 1);
    transpose_w_kernel<<<(N_LAYERS * 3 * HID * HID + 255) / 256, 256>>>(wih, whh);
    zero_agg_kernel<<<(N_NODES * HID / 4 + 255) / 256, 256>>>();

    for (int l = 0; l < N_LAYERS; l++) {
        // P = h @ W1h + b1
        pdense<<<dim3(148, 1), 256, PD_SMEM>>>(
            hp, w1 + (size_t)l * 144 * 128, b1 + l * 128, pp,
            hp, w1 + (size_t)l * 144 * 128, b1 + l * 128, pp,
            N_NODES, 128, 128, 1, 0);
        // edge MLP + scatter into agg
        edge_kernel<<<148, 256, EDGE_SMEM>>>(
            eattr, eidx, eidx + N_EDGES,
            w1 + (size_t)l * 144 * 128 + 128 * 128,
            w2 + (size_t)l * 128 * 128, b2 + l * 128);
        // gi = agg @ wihT + bih  |  gh = h @ whhT + bhh   (one launch, 6 slabs)
        pdense<<<dim3(24, 6), 256, PD_SMEM>>>(
            aggp, wihTp + (size_t)l * 128 * 384, bih + l * 384, gip,
            hp,   whhTp + (size_t)l * 128 * 384, bhh + l * 384, ghp,
            N_NODES, 384, 384, 3, 0);
        // gates + BN + residual (+ zero agg for next layer)
        gru_epi_kernel<<<(N_NODES * HID + 255) / 256, 256>>>(
            bng + l * 128, bnb + l * 128, bnm + l * 128, bnv + l * 128);
    }

    zero_readout_kernel<<<(N_GRAPHS * HID + 255) / 256, 256>>>();
    readout_acc_kernel<<<(N_NODES + 127) / 128, 128>>>(batch);
    readout_final_kernel<<<N_GRAPHS, HID>>>(roW, roB, out);
}

// round 6
// speedup vs baseline: 6.0094x; 1.0326x over previous
#include <cuda_runtime.h>
#include <math.h>
#include <stdint.h>

#define N_NODES   50000
#define N_EDGES   800000
#define IN_DIM    128
#define EDGE_DIM  16
#define HID       128
#define N_LAYERS  3
#define N_GRAPHS  256
#define BN_EPS    1e-5f

// fragment-major weight block: 64 (ks,tg) slots x 260 words (8 pad for banks)
#define FRAG_PITCH 260

// ---------------- scratch ----------------
__device__ float    g_h[N_NODES * HID];
__device__ float    g_agg[N_NODES * HID];
__device__ float    g_p[N_NODES * HID];
__device__ float    g_gi[N_NODES * 3 * HID];
__device__ float    g_gh[N_NODES * 3 * HID];
__device__ float    g_wihT[N_LAYERS * HID * 3 * HID];  // [l][k][o]
__device__ float    g_whhT[N_LAYERS * HID * 3 * HID];
__device__ float    g_rsum[N_GRAPHS * HID];
__device__ unsigned g_rmax[N_GRAPHS * HID];
__device__ int      g_rcnt[N_GRAPHS];

// ---------------- helpers ----------------
__device__ __forceinline__ unsigned fenc(float f) {
    unsigned u = __float_as_uint(f);
    return (u & 0x80000000u) ? ~u : (u | 0x80000000u);
}
__device__ __forceinline__ float fdec(unsigned k) {
    return __uint_as_float((k & 0x80000000u) ? (k & 0x7fffffffu) : ~k);
}
__device__ __forceinline__ unsigned f2tf(float f) {
    unsigned u;
    asm("cvt.rna.tf32.f32 %0, %1;" : "=r"(u) : "f"(f));
    return u;
}
__device__ __forceinline__ void mma_tf32(float* c, const unsigned* a,
                                         unsigned b0, unsigned b1) {
    asm volatile(
        "mma.sync.aligned.m16n8k8.row.col.f32.tf32.tf32.f32 "
        "{%0,%1,%2,%3}, {%4,%5,%6,%7}, {%8,%9}, {%0,%1,%2,%3};"
        : "+f"(c[0]), "+f"(c[1]), "+f"(c[2]), "+f"(c[3])
        : "r"(a[0]), "r"(a[1]), "r"(a[2]), "r"(a[3]), "r"(b0), "r"(b1));
}
__device__ __forceinline__ void cp16(uint32_t s, const void* g) {
    asm volatile("cp.async.cg.shared.global [%0], [%1], 16;" :: "r"(s), "l"(g));
}
__device__ __forceinline__ void red2(float* p, float a, float b) {
    asm volatile("red.global.add.v2.f32 [%0], {%1,%2};"
                 :: "l"(p), "f"(a), "f"(b) : "memory");
}

// pack a [K,128] row-major weight block (K = 8*nks rows) into fragment-major
// tf32 SMEM: slot (ks*4+tg)*FRAG_PITCH + ((wn*8+gid)*8+nt)*2 + pair
template<int NKS>
__device__ __forceinline__ void pack_wfrag(unsigned* sW, const float* __restrict__ W,
                                           int ldw, int n0, int tid, int nthr) {
    for (int i = tid; i < NKS * 1024; i += nthr) {
        int pair = i & 1, nt = (i >> 1) & 7, gid = (i >> 4) & 7;
        int wn = (i >> 7) & 1, tg = (i >> 8) & 3, ks = i >> 10;
        int row = ks * 8 + tg + pair * 4;
        int col = wn * 64 + nt * 8 + gid;
        sW[(ks * 4 + tg) * FRAG_PITCH + ((wn * 8 + gid) * 8 + nt) * 2 + pair] =
            f2tf(__ldg(W + (size_t)row * ldw + n0 + col));
    }
}

// ---------------- zero / setup ----------------
__global__ void zero_agg_kernel() {
    int i = blockIdx.x * blockDim.x + threadIdx.x;
    if (i < (N_NODES * HID) / 4)
        ((float4*)g_agg)[i] = make_float4(0.f, 0.f, 0.f, 0.f);
}
__global__ void zero_readout_kernel() {
    int i = blockIdx.x * blockDim.x + threadIdx.x;
    if (i < N_GRAPHS * HID) { g_rsum[i] = 0.f; g_rmax[i] = 0u; }
    if (i < N_GRAPHS) g_rcnt[i] = 0;
}
__global__ void transpose_w_kernel(const float* __restrict__ wih,
                                   const float* __restrict__ whh) {
    int idx = blockIdx.x * blockDim.x + threadIdx.x;
    const int per_layer = 3 * HID * HID;
    if (idx >= N_LAYERS * per_layer) return;
    int l = idx / per_layer;
    int r = idx - l * per_layer;
    int o = r / HID;
    int k = r - o * HID;
    g_wihT[l * per_layer + k * (3 * HID) + o] = wih[idx];
    g_whhT[l * per_layer + k * (3 * HID) + o] = whh[idx];
}

// ---------------- persistent dense tf32 GEMM, 512 threads ----------------
#define PD_WORDS (64 * FRAG_PITCH + 2 * 128 * 132)
#define PD_SMEM  (PD_WORDS * 4)           // 201728 B
__global__ void __launch_bounds__(512, 1)
pdense(const float* __restrict__ Aa, const float* __restrict__ Ba,
       const float* __restrict__ biasa, float* __restrict__ Ca,
       const float* __restrict__ Ab, const float* __restrict__ Bb,
       const float* __restrict__ biasb, float* __restrict__ Cb,
       int M, int nB, int nC, int nslabA, int relu) {
    extern __shared__ unsigned psm[];
    unsigned* sB = psm;                              // 64 x 260 fragment-major
    float*    sA = (float*)(psm + 64 * FRAG_PITCH);  // 2 x (128 x 132)
    int slab = blockIdx.y;
    const float *A, *B, *bias; float* C; int n0;
    if (slab < nslabA) { A = Aa; B = Ba; bias = biasa; C = Ca; n0 = slab * 128; }
    else { A = Ab; B = Bb; bias = biasb; C = Cb; n0 = (slab - nslabA) * 128; }

    int tid = threadIdx.x, lane = tid & 31, wid = tid >> 5;
    int wm = wid & 7, wn = wid >> 3, gid = lane >> 2, tg = lane & 3;
    int r4 = tid >> 2, q = tid & 3;
    uint32_t sa_u32 = (uint32_t)__cvta_generic_to_shared(sA);

    const int tiles = (M + 127) >> 7;
    {
        int gm = blockIdx.x * 128 + r4; if (gm >= M) gm = M - 1;
        const float* ar = A + (size_t)gm * 128 + q * 32;
        uint32_t sa = sa_u32 + (r4 * 132 + q * 32) * 4;
#pragma unroll
        for (int k = 0; k < 8; k++) cp16(sa + k * 16, ar + k * 4);
        asm volatile("cp.async.commit_group;");
    }
    pack_wfrag<16>(sB, B, nB, n0, tid, 512);

    int buf = 0;
    for (int t = blockIdx.x; t < tiles; t += gridDim.x) {
        int tn = t + gridDim.x;
        if (tn < tiles) {
            int gm = tn * 128 + r4; if (gm >= M) gm = M - 1;
            const float* ar = A + (size_t)gm * 128 + q * 32;
            uint32_t sa = sa_u32 + ((buf ^ 1) * 128 * 132 + r4 * 132 + q * 32) * 4;
#pragma unroll
            for (int k = 0; k < 8; k++) cp16(sa + k * 16, ar + k * 4);
        }
        asm volatile("cp.async.commit_group;");
        asm volatile("cp.async.wait_group 1;");
        __syncthreads();

        const unsigned* sAu = (const unsigned*)(sA + buf * 128 * 132);
        float acc[8][4];
#pragma unroll
        for (int nt = 0; nt < 8; nt++)
#pragma unroll
            for (int i = 0; i < 4; i++) acc[nt][i] = 0.f;

        int R = wm * 16 + gid;
#pragma unroll 4
        for (int ks = 0; ks < 16; ks++) {
            unsigned a[4];
            int col = ks * 8 + tg;
            a[0] = sAu[R * 132 + col];
            a[1] = sAu[(R + 8) * 132 + col];
            a[2] = sAu[R * 132 + col + 4];
            a[3] = sAu[(R + 8) * 132 + col + 4];
            const uint4* bp = (const uint4*)(sB + (ks * 4 + tg) * FRAG_PITCH
                                             + (wn * 8 + gid) * 16);
#pragma unroll
            for (int j = 0; j < 4; j++) {
                uint4 b = bp[j];
                mma_tf32(acc[2 * j],     a, b.x, b.y);
                mma_tf32(acc[2 * j + 1], a, b.z, b.w);
            }
        }

        int m0 = t * 128;
#pragma unroll
        for (int nt = 0; nt < 8; nt++)
#pragma unroll
            for (int p = 0; p < 2; p++) {
                int gm = m0 + R + p * 8;
                if (gm < M) {
                    int col = wn * 64 + nt * 8 + 2 * tg;
                    float2 v;
                    v.x = acc[nt][p * 2]     + __ldg(bias + n0 + col);
                    v.y = acc[nt][p * 2 + 1] + __ldg(bias + n0 + col + 1);
                    if (relu) { v.x = fmaxf(v.x, 0.f); v.y = fmaxf(v.y, 0.f); }
                    *(float2*)(C + (size_t)gm * nC + n0 + col) = v;
                }
            }
        __syncthreads();
        buf ^= 1;
    }
}

// ---------------- edge kernel, 512 threads ----------------
#define OFF_W2   0
#define OFF_W1E  (64 * FRAG_PITCH)                   // 16640
#define OFF_A    (OFF_W1E + 8 * FRAG_PITCH)          // 18720
#define OFF_E    (OFF_A + 2 * 128 * 132)             // 52512
#define EDGE_WORDS (OFF_E + 2 * 128 * 20)            // 57632
#define EDGE_SMEM (EDGE_WORDS * 4)                   // 230528 B

__global__ void __launch_bounds__(512, 1)
edge_kernel(const float* __restrict__ eattr,
            const int* __restrict__ src,
            const int* __restrict__ dst,
            const float* __restrict__ W1e,
            const float* __restrict__ W2,
            const float* __restrict__ b2) {
    extern __shared__ unsigned smu[];
    unsigned* sW2  = smu + OFF_W2;
    unsigned* sW1e = smu + OFF_W1E;
    float*    smf  = (float*)smu;
    __shared__ float sB2[128];
    uint32_t smem_u32 = (uint32_t)__cvta_generic_to_shared(smu);

    int tid = threadIdx.x, lane = tid & 31, wid = tid >> 5;
    int wm = wid & 7, wn = wid >> 3, gid = lane >> 2, tg = lane & 3;
    int r4 = tid >> 2, q = tid & 3;

    {
        int e0 = blockIdx.x * 128;
        int s = __ldg(src + e0 + r4);
        const float* pr = g_p + (size_t)s * HID + q * 32;
        uint32_t sa = smem_u32 + (OFF_A + r4 * 132 + q * 32) * 4;
#pragma unroll
        for (int k = 0; k < 8; k++) cp16(sa + k * 16, pr + k * 4);
        const float* er = eattr + (size_t)(e0 + r4) * EDGE_DIM + q * 4;
        cp16(smem_u32 + (OFF_E + r4 * 20 + q * 4) * 4, er);
        asm volatile("cp.async.commit_group;");
    }
    pack_wfrag<16>(sW2, W2, 128, 0, tid, 512);
    pack_wfrag<2>(sW1e, W1e, 128, 0, tid, 512);
    if (tid < 128) sB2[tid] = b2[tid];

    const int ntiles = N_EDGES / 128;  // 6250
    int buf = 0;
    for (int t = blockIdx.x; t < ntiles; t += gridDim.x) {
        int tn = t + gridDim.x;
        if (tn < ntiles) {
            int e0n = tn * 128;
            int s = __ldg(src + e0n + r4);
            const float* pr = g_p + (size_t)s * HID + q * 32;
            uint32_t sa = smem_u32 + (OFF_A + (buf ^ 1) * (128 * 132) + r4 * 132 + q * 32) * 4;
#pragma unroll
            for (int k = 0; k < 8; k++) cp16(sa + k * 16, pr + k * 4);
            const float* er = eattr + (size_t)(e0n + r4) * EDGE_DIM + q * 4;
            cp16(smem_u32 + (OFF_E + (buf ^ 1) * (128 * 20) + r4 * 20 + q * 4) * 4, er);
        }
        asm volatile("cp.async.commit_group;");
        asm volatile("cp.async.wait_group 1;");
        __syncthreads();

        float*    sAf = smf + OFF_A + buf * (128 * 132);
        unsigned* sAu = (unsigned*)sAf;
        unsigned* sEu = smu + OFF_E + buf * (128 * 20);
        int e0 = t * 128;
        int R = wm * 16 + gid;

        // stage 1: acc = P[src] + eattr@W1e (K=16), relu -> hidden (tf32)
        float acc[8][4];
#pragma unroll
        for (int nt = 0; nt < 8; nt++) {
            int Cc = wn * 64 + nt * 8 + 2 * tg;
            float2 v0 = *(float2*)(sAf + R * 132 + Cc);
            float2 v1 = *(float2*)(sAf + (R + 8) * 132 + Cc);
            acc[nt][0] = v0.x; acc[nt][1] = v0.y;
            acc[nt][2] = v1.x; acc[nt][3] = v1.y;
        }
#pragma unroll
        for (int ks = 0; ks < 2; ks++) {
            unsigned a[4];
            int col = ks * 8 + tg;
            a[0] = sEu[R * 20 + col];
            a[1] = sEu[(R + 8) * 20 + col];
            a[2] = sEu[R * 20 + col + 4];
            a[3] = sEu[(R + 8) * 20 + col + 4];
            const uint4* bp = (const uint4*)(sW1e + (ks * 4 + tg) * FRAG_PITCH
                                             + (wn * 8 + gid) * 16);
#pragma unroll
            for (int j = 0; j < 4; j++) {
                uint4 b = bp[j];
                mma_tf32(acc[2 * j],     a, b.x, b.y);
                mma_tf32(acc[2 * j + 1], a, b.z, b.w);
            }
        }
#pragma unroll
        for (int nt = 0; nt < 8; nt++)
#pragma unroll
            for (int i = 0; i < 4; i++) {
                int row = R + ((i >> 1) << 3);
                int col = wn * 64 + nt * 8 + 2 * tg + (i & 1);
                sAu[row * 132 + col] = f2tf(fmaxf(acc[nt][i], 0.f));
            }
        __syncthreads();

        // stage 2: m = hidden @ W2 (K=128)
#pragma unroll
        for (int nt = 0; nt < 8; nt++)
#pragma unroll
            for (int i = 0; i < 4; i++) acc[nt][i] = 0.f;
#pragma unroll 4
        for (int ks = 0; ks < 16; ks++) {
            unsigned a[4];
            int col = ks * 8 + tg;
            a[0] = sAu[R * 132 + col];
            a[1] = sAu[(R + 8) * 132 + col];
            a[2] = sAu[R * 132 + col + 4];
            a[3] = sAu[(R + 8) * 132 + col + 4];
            const uint4* bp = (const uint4*)(sW2 + (ks * 4 + tg) * FRAG_PITCH
                                             + (wn * 8 + gid) * 16);
#pragma unroll
            for (int j = 0; j < 4; j++) {
                uint4 b = bp[j];
                mma_tf32(acc[2 * j],     a, b.x, b.y);
                mma_tf32(acc[2 * j + 1], a, b.z, b.w);
            }
        }
        __syncthreads();  // all warps done with sAu before next prefetch reuse

        // epilogue: direct red.v2 from registers
        int d0 = __ldg(dst + e0 + R);
        int d1 = __ldg(dst + e0 + R + 8);
#pragma unroll
        for (int nt = 0; nt < 8; nt++) {
            int col = wn * 64 + nt * 8 + 2 * tg;
            float bb0 = sB2[col], bb1 = sB2[col + 1];
            red2(&g_agg[(size_t)d0 * HID + col], acc[nt][0] + bb0, acc[nt][1] + bb1);
            red2(&g_agg[(size_t)d1 * HID + col], acc[nt][2] + bb0, acc[nt][3] + bb1);
        }
        buf ^= 1;
    }
}

// ---------------- GRU gates + BN + residual (+ zero agg) ----------------
__global__ void gru_epi_kernel(const float* __restrict__ gamma,
                               const float* __restrict__ beta,
                               const float* __restrict__ mean,
                               const float* __restrict__ var) {
    int idx = blockIdx.x * blockDim.x + threadIdx.x;
    if (idx >= N_NODES * HID) return;
    int n = idx >> 7, j = idx & 127;
    const float* gi = g_gi + (size_t)n * 384;
    const float* gh = g_gh + (size_t)n * 384;
    float ir = gi[j], iz = gi[128 + j], inn = gi[256 + j];
    float hr = gh[j], hz = gh[128 + j], hn  = gh[256 + j];
    float h = g_h[idx];
    float r = 1.f / (1.f + __expf(-(ir + hr)));
    float z = 1.f / (1.f + __expf(-(iz + hz)));
    float nn = tanhf(inn + r * hn);
    float hnew = (1.f - z) * nn + z * h;
    float bn = (hnew - mean[j]) * rsqrtf(var[j] + BN_EPS) * gamma[j] + beta[j];
    g_h[idx] = h + bn;
    g_agg[idx] = 0.f;
}

// ---------------- readout ----------------
__global__ void readout_acc_kernel(const int* __restrict__ batch) {
    __shared__ int sb[128];
    int j = threadIdx.x;
    int nBeg = blockIdx.x * 128;
    int cnt = min(128, N_NODES - nBeg);
    sb[j] = (j < cnt) ? __ldg(batch + nBeg + j) : -1;
    __syncthreads();
    int curb = sb[0];
    float s = 0.f; unsigned mx = 0u; int c = 0;
    for (int i = 0; i < cnt; i++) {
        int b = sb[i];
        float v = g_h[(size_t)(nBeg + i) * HID + j];
        if (b != curb) {
            atomicAdd(&g_rsum[curb * HID + j], s);
            atomicMax(&g_rmax[curb * HID + j], mx);
            if (j == 0) atomicAdd(&g_rcnt[curb], c);
            s = 0.f; mx = 0u; c = 0; curb = b;
        }
        s += v; mx = max(mx, fenc(v)); c++;
    }
    if (c > 0) {
        atomicAdd(&g_rsum[curb * HID + j], s);
        atomicMax(&g_rmax[curb * HID + j], mx);
        if (j == 0) atomicAdd(&g_rcnt[curb], c);
    }
}
__global__ void readout_final_kernel(const float* __restrict__ roW,
                                     const float* __restrict__ roB,
                                     float* __restrict__ out) {
    __shared__ float s[2 * HID];
    int g = blockIdx.x, j = threadIdx.x;
    int cnt = g_rcnt[g];
    float mv = g_rsum[g * HID + j] / fmaxf((float)cnt, 1.f);
    float xv = (cnt > 0) ? fdec(g_rmax[g * HID + j]) : 0.f;
    s[j] = mv;
    s[HID + j] = xv;
    __syncthreads();
    float acc = roB[j];
    for (int k = 0; k < 2 * HID; k++) acc += s[k] * roW[k * HID + j];
    out[g * HID + j] = fmaxf(acc, 0.f);
}

// ---------------- launch ----------------
extern "C" void kernel_launch(void* const* d_in, const int* in_sizes, int n_in,
                              void* d_out, int out_size) {
    int base = (in_sizes[4] <= 2) ? 5 : 4;
    const float* x     = (const float*)d_in[0];
    const int*   eidx  = (const int*)d_in[1];
    const float* eattr = (const float*)d_in[2];
    const int*   batch = (const int*)d_in[3];
    const float* linW  = (const float*)d_in[base + 0];
    const float* linB  = (const float*)d_in[base + 1];
    const float* w1    = (const float*)d_in[base + 2];
    const float* b1    = (const float*)d_in[base + 3];
    const float* w2    = (const float*)d_in[base + 4];
    const float* b2    = (const float*)d_in[base + 5];
    const float* bng   = (const float*)d_in[base + 6];
    const float* bnb   = (const float*)d_in[base + 7];
    const float* bnm   = (const float*)d_in[base + 8];
    const float* bnv   = (const float*)d_in[base + 9];
    const float* wih   = (const float*)d_in[base + 10];
    const float* whh   = (const float*)d_in[base + 11];
    const float* bih   = (const float*)d_in[base + 12];
    const float* bhh   = (const float*)d_in[base + 13];
    const float* roW   = (const float*)d_in[base + 14];
    const float* roB   = (const float*)d_in[base + 15];
    float* out = (float*)d_out;

    cudaFuncSetAttribute(pdense,      cudaFuncAttributeMaxDynamicSharedMemorySize, PD_SMEM);
    cudaFuncSetAttribute(edge_kernel, cudaFuncAttributeMaxDynamicSharedMemorySize, EDGE_SMEM);

    float *hp, *aggp, *pp, *gip, *ghp, *wihTp, *whhTp;
    cudaGetSymbolAddress((void**)&hp,    g_h);
    cudaGetSymbolAddress((void**)&aggp,  g_agg);
    cudaGetSymbolAddress((void**)&pp,    g_p);
    cudaGetSymbolAddress((void**)&gip,   g_gi);
    cudaGetSymbolAddress((void**)&ghp,   g_gh);
    cudaGetSymbolAddress((void**)&wihTp, g_wihT);
    cudaGetSymbolAddress((void**)&whhTp, g_whhT);

    // h = relu(x @ linW + linB)
    pdense<<<dim3(148, 1), 512, PD_SMEM>>>(x, linW, linB, hp,
                                           x, linW, linB, hp,
                                           N_NODES, 128, 128, 1, 1);
    transpose_w_kernel<<<(N_LAYERS * 3 * HID * HID + 255) / 256, 256>>>(wih, whh);
    zero_agg_kernel<<<(N_NODES * HID / 4 + 255) / 256, 256>>>();

    for (int l = 0; l < N_LAYERS; l++) {
        // P = h @ W1h + b1
        pdense<<<dim3(148, 1), 512, PD_SMEM>>>(
            hp, w1 + (size_t)l * 144 * 128, b1 + l * 128, pp,
            hp, w1 + (size_t)l * 144 * 128, b1 + l * 128, pp,
            N_NODES, 128, 128, 1, 0);
        // edge MLP + scatter into agg
        edge_kernel<<<148, 512, EDGE_SMEM>>>(
            eattr, eidx, eidx + N_EDGES,
            w1 + (size_t)l * 144 * 128 + 128 * 128,
            w2 + (size_t)l * 128 * 128, b2 + l * 128);
        // gi = agg @ wihT + bih  |  gh = h @ whhT + bhh
        pdense<<<dim3(24, 6), 512, PD_SMEM>>>(
            aggp, wihTp + (size_t)l * 128 * 384, bih + l * 384, gip,
            hp,   whhTp + (size_t)l * 128 * 384, bhh + l * 384, ghp,
            N_NODES, 384, 384, 3, 0);
        gru_epi_kernel<<<(N_NODES * HID + 255) / 256, 256>>>(
            bng + l * 128, bnb + l * 128, bnm + l * 128, bnv + l * 128);
    }

    zero_readout_kernel<<<(N_GRAPHS * HID + 255) / 256, 256>>>();
    readout_acc_kernel<<<(N_NODES + 127) / 128, 128>>>(batch);
    readout_final_kernel<<<N_GRAPHS, HID>>>(roW, roB, out);
}